// round 3
// baseline (speedup 1.0000x reference)
#include <cuda_runtime.h>
#include <math.h>

#define NPTS 4096
#define DS 48
#define DA 16
#define DF 64
#define NB 8192
#define RANGE1 16.0f
#define SCALE1 ((float)NB / RANGE1)   /* 512 */
#define TB 128
#define NTILE (NPTS / TB)             /* 32 */

// ---------------- device scratch (no allocs allowed) ----------------
__device__ float  g_Dae[(size_t)NPTS * NPTS];   // 64 MB
__device__ float  g_Dee[(size_t)NPTS * NPTS];   // 64 MB
__device__ float  g_x2[NPTS];                   // |sa_i|^2
__device__ float  g_y2[NPTS];                   // |esa_j|^2
__device__ float  g_hist[4 * NB];               // [aeL1, eeL1, aeL2, eeL2]
__device__ double g_scal[8];                    // 0 Wsum, 1 EWsum, 2 cumBefore_ae, 3 cumBefore_ee, 4 g1, 5 g2
__device__ int    g_bin[2];                     // level-1 chosen bin (ae, ee)
__device__ float  g_Sae[NPTS];
__device__ float  g_Saa[NPTS];

// ---------------- zero per-replay accumulators ----------------
__global__ void k_zero() {
    int i = blockIdx.x * blockDim.x + threadIdx.x;
    if (i < 4 * NB) g_hist[i] = 0.f;
    if (i < NPTS)   g_Saa[i]  = 0.f;
}

// ---------------- row norms of concat(state, action) ----------------
__global__ void k_norms(const float* __restrict__ ss, const float* __restrict__ sa,
                        const float* __restrict__ es, const float* __restrict__ ea) {
    int i = blockIdx.x * blockDim.x + threadIdx.x;
    if (i < NPTS) {
        float s = 0.f;
        #pragma unroll
        for (int k = 0; k < DS; k++) { float v = ss[(size_t)i * DS + k]; s += v * v; }
        #pragma unroll
        for (int k = 0; k < DA; k++) { float v = sa[(size_t)i * DA + k]; s += v * v; }
        g_x2[i] = s;
    } else if (i < 2 * NPTS) {
        int j = i - NPTS;
        float s = 0.f;
        #pragma unroll
        for (int k = 0; k < DS; k++) { float v = es[(size_t)j * DS + k]; s += v * v; }
        #pragma unroll
        for (int k = 0; k < DA; k++) { float v = ea[(size_t)j * DA + k]; s += v * v; }
        g_y2[j] = s;
    }
}

// ---------------- weight sums (double) ----------------
__global__ void k_wsum(const float* __restrict__ w, const float* __restrict__ ew) {
    __shared__ double sh[1024];
    int tid = threadIdx.x;
    double s1 = 0.0, s2 = 0.0;
    for (int i = tid; i < NPTS; i += 1024) { s1 += w[i]; s2 += ew[i]; }
    sh[tid] = s1; __syncthreads();
    for (int off = 512; off; off >>= 1) { if (tid < off) sh[tid] += sh[tid + off]; __syncthreads(); }
    if (tid == 0) g_scal[0] = sh[0];
    __syncthreads();
    sh[tid] = s2; __syncthreads();
    for (int off = 512; off; off >>= 1) { if (tid < off) sh[tid] += sh[tid + off]; __syncthreads(); }
    if (tid == 0) g_scal[1] = sh[0];
}

// ---------------- distance tile + store + level-1 weighted histogram ----------------
// 128x128 output tile per block, 256 threads, 8x8 micro-tile per thread.
// smem: As[64][128] (k-major), Bs[64][128], hist[8192], x2/y2/wx/wy tiles.
__global__ void __launch_bounds__(256) k_dist(
    const float* __restrict__ xs_s, const float* __restrict__ xs_a,
    const float* __restrict__ ys_s, const float* __restrict__ ys_a,
    const float* __restrict__ x2v, const float* __restrict__ y2v,
    const float* __restrict__ wxv, const float* __restrict__ wyv,
    float* __restrict__ Dout, float* __restrict__ hist)
{
    extern __shared__ float sm[];
    float* As   = sm;                  // DF*TB
    float* Bs   = As + DF * TB;        // DF*TB
    float* shh  = Bs + DF * TB;        // NB
    float* shx2 = shh + NB;            // TB
    float* shy2 = shx2 + TB;
    float* shwx = shy2 + TB;
    float* shwy = shwx + TB;

    int tid  = threadIdx.x;
    int row0 = blockIdx.y * TB;
    int col0 = blockIdx.x * TB;

    for (int i = tid; i < NB; i += 256) shh[i] = 0.f;

    for (int e = tid; e < TB * DF; e += 256) {
        int r = e >> 6, k = e & 63;
        As[k * TB + r] = (k < DS) ? xs_s[(size_t)(row0 + r) * DS + k]
                                  : xs_a[(size_t)(row0 + r) * DA + (k - DS)];
        Bs[k * TB + r] = (k < DS) ? ys_s[(size_t)(col0 + r) * DS + k]
                                  : ys_a[(size_t)(col0 + r) * DA + (k - DS)];
    }
    if (tid < TB) {
        shx2[tid] = x2v[row0 + tid];
        shy2[tid] = y2v[col0 + tid];
        shwx[tid] = wxv[row0 + tid];
        shwy[tid] = wyv[col0 + tid];
    }
    __syncthreads();

    int tx = tid & 15, ty = tid >> 4;
    int ra = ty * 8, cb = tx * 8;

    float acc[8][8];
    #pragma unroll
    for (int r = 0; r < 8; r++)
        #pragma unroll
        for (int c = 0; c < 8; c++) acc[r][c] = 0.f;

    #pragma unroll 4
    for (int k = 0; k < DF; k++) {
        float a[8], b[8];
        *(float4*)&a[0] = *(const float4*)&As[k * TB + ra];
        *(float4*)&a[4] = *(const float4*)&As[k * TB + ra + 4];
        *(float4*)&b[0] = *(const float4*)&Bs[k * TB + cb];
        *(float4*)&b[4] = *(const float4*)&Bs[k * TB + cb + 4];
        #pragma unroll
        for (int r = 0; r < 8; r++)
            #pragma unroll
            for (int c = 0; c < 8; c++)
                acc[r][c] = fmaf(a[r], b[c], acc[r][c]);
    }

    #pragma unroll
    for (int r = 0; r < 8; r++) {
        int gr = row0 + ra + r;
        float x2r = shx2[ra + r];
        float wr  = shwx[ra + r];
        float d[8];
        #pragma unroll
        for (int c = 0; c < 8; c++) {
            d[c] = fmaxf(x2r + shy2[cb + c] - 2.f * acc[r][c], 0.f) * (1.f / DF);
            int bb = (int)(d[c] * SCALE1);
            bb = bb > NB - 1 ? NB - 1 : bb;
            atomicAdd(&shh[bb], wr * shwy[cb + c]);
        }
        float4* o = (float4*)&Dout[(size_t)gr * NPTS + col0 + cb];
        o[0] = make_float4(d[0], d[1], d[2], d[3]);
        o[1] = make_float4(d[4], d[5], d[6], d[7]);
    }
    __syncthreads();
    for (int i = tid; i < NB; i += 256) {
        float v = shh[i];
        if (v != 0.f) atomicAdd(&hist[i], v);
    }
}

// ---------------- weighted-median scan (level 0 and 1), 2 blocks (ae, ee) ----------------
__global__ void k_median(int level) {
    int which = blockIdx.x;                 // 0 = ae, 1 = ee
    const float* h = g_hist + ((level ? 2 : 0) + which) * NB;
    double Wtot = (which == 0) ? g_scal[0] * g_scal[1] : g_scal[1] * g_scal[1];
    double T = 0.5 * Wtot;
    if (level) T -= g_scal[2 + which];

    __shared__ double part[1024];
    int tid = threadIdx.x;
    double loc[8];
    double s = 0.0;
    #pragma unroll
    for (int i = 0; i < 8; i++) { loc[i] = h[tid * 8 + i]; s += loc[i]; }
    part[tid] = s;
    __syncthreads();
    for (int off = 1; off < 1024; off <<= 1) {
        double v = (tid >= off) ? part[tid - off] : 0.0;
        __syncthreads();
        part[tid] += v;
        __syncthreads();
    }
    double c = (tid == 0) ? 0.0 : part[tid - 1];
    bool found = false;
    #pragma unroll
    for (int i = 0; i < 8; i++) {
        double nc = c + loc[i];
        if (!found && c < T && nc >= T) {
            found = true;
            int b = tid * 8 + i;
            if (level == 0) {
                g_bin[which] = b;
                g_scal[2 + which] = c;      // cumulative weight strictly before bin b
            } else {
                double w1 = (double)RANGE1 / NB;
                double w2 = w1 / NB;
                double t = (double)g_bin[which] * w1 + ((double)b + 0.5) * w2;
                g_scal[4 + which] = 1.0 / (t + 1e-8);
            }
        }
        c = nc;
    }
    // fallback: total mass (fp-rounded) never reached T
    if (tid == 1023 && part[1023] < T) {
        if (level == 0) {
            g_bin[which] = NB - 1;
            g_scal[2 + which] = part[1023] - loc[7];
        } else {
            double w1 = (double)RANGE1 / NB, w2 = w1 / NB;
            double t = (double)g_bin[which] * w1 + ((double)NB - 0.5) * w2;
            g_scal[4 + which] = 1.0 / (t + 1e-8);
        }
    }
}

// ---------------- level-2 histogram inside the chosen level-1 bin ----------------
__global__ void k_hist2(const float* __restrict__ D, const float* __restrict__ wx,
                        const float* __restrict__ wy, int which)
{
    __shared__ float shh[NB];
    int tid = threadIdx.x;
    for (int i = tid; i < NB; i += 256) shh[i] = 0.f;
    __syncthreads();
    int b1 = g_bin[which];
    float lo  = (float)b1 * (RANGE1 / NB);
    float sc2 = SCALE1 * (float)NB;
    size_t total = (size_t)NPTS * NPTS;
    for (size_t idx = (size_t)blockIdx.x * 256 + tid; idx < total; idx += (size_t)gridDim.x * 256) {
        float v = D[idx];
        int bb = (int)(v * SCALE1);
        bb = bb > NB - 1 ? NB - 1 : bb;
        if (bb == b1) {
            int i = (int)(idx >> 12);
            int j = (int)(idx & (NPTS - 1));
            int b2 = (int)((v - lo) * sc2);
            b2 = b2 < 0 ? 0 : (b2 > NB - 1 ? NB - 1 : b2);
            atomicAdd(&shh[b2], wx[i] * wy[j]);
        }
    }
    __syncthreads();
    float* out = g_hist + (2 + which) * NB;
    for (int i = tid; i < NB; i += 256) {
        float v = shh[i];
        if (v != 0.f) atomicAdd(&out[i], v);
    }
}

// ---------------- kernel-sum over stored D_ae: S_ae[i] = sum_j K(D) * ew[j] ----------------
__global__ void k_sumae(const float* __restrict__ ew) {
    int i = blockIdx.x;
    float G1 = (float)g_scal[4], G2 = (float)g_scal[5];
    const float* row = g_Dae + (size_t)i * NPTS;
    float s = 0.f;
    for (int j = threadIdx.x; j < NPTS; j += 256) {
        float dd = row[j];
        s += (__expf(-G1 * dd) + __expf(-G2 * dd)) * ew[j];
    }
    __shared__ float red[256];
    red[threadIdx.x] = s; __syncthreads();
    for (int off = 128; off; off >>= 1) {
        if (threadIdx.x < off) red[threadIdx.x] += red[threadIdx.x + off];
        __syncthreads();
    }
    if (threadIdx.x == 0) g_Sae[i] = red[0];
}

// ---------------- fused D_aa + kernel-sum (no store) ----------------
__global__ void __launch_bounds__(256) k_aa(
    const float* __restrict__ xs_s, const float* __restrict__ xs_a,
    const float* __restrict__ wv)
{
    extern __shared__ float sm[];
    float* As     = sm;
    float* Bs     = As + DF * TB;
    float* shx2   = Bs + DF * TB;
    float* shy2   = shx2 + TB;
    float* shwy   = shy2 + TB;
    float* rowsum = shwy + TB;   // TB floats

    int tid  = threadIdx.x;
    int row0 = blockIdx.y * TB;
    int col0 = blockIdx.x * TB;

    if (tid < TB) rowsum[tid] = 0.f;

    for (int e = tid; e < TB * DF; e += 256) {
        int r = e >> 6, k = e & 63;
        As[k * TB + r] = (k < DS) ? xs_s[(size_t)(row0 + r) * DS + k]
                                  : xs_a[(size_t)(row0 + r) * DA + (k - DS)];
        Bs[k * TB + r] = (k < DS) ? xs_s[(size_t)(col0 + r) * DS + k]
                                  : xs_a[(size_t)(col0 + r) * DA + (k - DS)];
    }
    if (tid < TB) {
        shx2[tid] = g_x2[row0 + tid];
        shy2[tid] = g_x2[col0 + tid];
        shwy[tid] = wv[col0 + tid];
    }
    __syncthreads();

    float G1 = (float)g_scal[4], G2 = (float)g_scal[5];

    int tx = tid & 15, ty = tid >> 4;
    int ra = ty * 8, cb = tx * 8;

    float acc[8][8];
    #pragma unroll
    for (int r = 0; r < 8; r++)
        #pragma unroll
        for (int c = 0; c < 8; c++) acc[r][c] = 0.f;

    #pragma unroll 4
    for (int k = 0; k < DF; k++) {
        float a[8], b[8];
        *(float4*)&a[0] = *(const float4*)&As[k * TB + ra];
        *(float4*)&a[4] = *(const float4*)&As[k * TB + ra + 4];
        *(float4*)&b[0] = *(const float4*)&Bs[k * TB + cb];
        *(float4*)&b[4] = *(const float4*)&Bs[k * TB + cb + 4];
        #pragma unroll
        for (int r = 0; r < 8; r++)
            #pragma unroll
            for (int c = 0; c < 8; c++)
                acc[r][c] = fmaf(a[r], b[c], acc[r][c]);
    }

    #pragma unroll
    for (int r = 0; r < 8; r++) {
        float x2r = shx2[ra + r];
        float rs = 0.f;
        #pragma unroll
        for (int c = 0; c < 8; c++) {
            float dd = fmaxf(x2r + shy2[cb + c] - 2.f * acc[r][c], 0.f) * (1.f / DF);
            rs += (__expf(-G1 * dd) + __expf(-G2 * dd)) * shwy[cb + c];
        }
        atomicAdd(&rowsum[ra + r], rs);
    }
    __syncthreads();
    if (tid < TB) atomicAdd(&g_Saa[row0 + tid], rowsum[tid]);
}

// ---------------- final combine ----------------
__global__ void k_combine(const float* __restrict__ w, float* __restrict__ out) {
    int i = blockIdx.x * blockDim.x + threadIdx.x;
    if (i < NPTS) {
        float Ws  = (float)g_scal[0];
        float EWs = (float)g_scal[1];
        out[i] = (w[i] / Ws) * (g_Sae[i] / EWs - g_Saa[i] / Ws);
    }
}

// ---------------- host launcher ----------------
extern "C" void kernel_launch(void* const* d_in, const int* in_sizes, int n_in,
                              void* d_out, int out_size)
{
    const float* state   = (const float*)d_in[0];
    const float* action  = (const float*)d_in[1];
    const float* estate  = (const float*)d_in[2];
    const float* eaction = (const float*)d_in[3];
    const float* w       = (const float*)d_in[4];
    const float* ew      = (const float*)d_in[5];
    float* out = (float*)d_out;

    const int SMEM_DIST = (DF * TB * 2 + NB + 4 * TB) * (int)sizeof(float);   // 100352 B
    const int SMEM_AA   = (DF * TB * 2 + 4 * TB) * (int)sizeof(float);        // 67584 B

    cudaFuncSetAttribute(k_dist, cudaFuncAttributeMaxDynamicSharedMemorySize, SMEM_DIST);
    cudaFuncSetAttribute(k_aa,   cudaFuncAttributeMaxDynamicSharedMemorySize, SMEM_AA);

    float *p_x2, *p_y2, *p_hist, *p_Dae, *p_Dee;
    cudaGetSymbolAddress((void**)&p_x2,   g_x2);
    cudaGetSymbolAddress((void**)&p_y2,   g_y2);
    cudaGetSymbolAddress((void**)&p_hist, g_hist);
    cudaGetSymbolAddress((void**)&p_Dae,  g_Dae);
    cudaGetSymbolAddress((void**)&p_Dee,  g_Dee);

    dim3 grid(NTILE, NTILE);

    k_zero<<<128, 256>>>();
    k_norms<<<32, 256>>>(state, action, estate, eaction);
    k_wsum<<<1, 1024>>>(w, ew);

    // D_ae (store + level-1 hist), D_ee (store + level-1 hist)
    k_dist<<<grid, 256, SMEM_DIST>>>(state, action, estate, eaction,
                                     p_x2, p_y2, w, ew, p_Dae, p_hist);
    k_dist<<<grid, 256, SMEM_DIST>>>(estate, eaction, estate, eaction,
                                     p_y2, p_y2, ew, ew, p_Dee, p_hist + NB);

    k_median<<<2, 1024>>>(0);

    k_hist2<<<1024, 256>>>(p_Dae, w,  ew, 0);
    k_hist2<<<1024, 256>>>(p_Dee, ew, ew, 1);

    k_median<<<2, 1024>>>(1);

    k_sumae<<<NPTS, 256>>>(ew);
    k_aa<<<grid, 256, SMEM_AA>>>(state, action, w);

    k_combine<<<16, 256>>>(w, out);
}

// round 4
// speedup vs baseline: 1.0255x; 1.0255x over previous
#include <cuda_runtime.h>
#include <math.h>

#define NPTS 4096
#define DS 48
#define DA 16
#define DF 64
#define TB 128
#define NTILE (NPTS / TB)      /* 32 */
#define NTRI  528              /* 32*33/2 upper-tri tiles */
#define NB1 2048               /* coarse (sampled) bins over [0,16] */
#define SC1 128.0f             /* NB1/16 */
#define NBF 8192               /* fine bins per refine pass */

// ---------------- device scratch ----------------
__device__ float  g_Dae[(size_t)NPTS * NPTS];   // 64 MB
__device__ float  g_Dee[(size_t)NPTS * NPTS];   // 64 MB (upper-tri tiles valid)
__device__ float  g_x2[NPTS];
__device__ float  g_y2[NPTS];
__device__ float  g_hcoarse[2 * NB1];           // sampled L1 hist: ae, ee
__device__ float  g_hfine[4 * NBF];             // B_ae, B_ee, C_ae, C_ee
__device__ double g_below[4];                   // below-window mass per refine
__device__ double g_scal[8];                    // 0 Wsum,1 EWsum,2/3 lo/width ae,4/5 lo/width ee,6 g1,7 g2
__device__ float  g_Sae[NPTS];
__device__ float  g_Saa[NPTS];

// ---------------- zero per-replay accumulators ----------------
__global__ void k_zero() {
    int i = blockIdx.x * blockDim.x + threadIdx.x;
    if (i < 2 * NB1)  g_hcoarse[i] = 0.f;
    if (i < 4 * NBF)  g_hfine[i]   = 0.f;
    if (i < NPTS)     g_Saa[i]     = 0.f;
    if (i < 4)        g_below[i]   = 0.0;
}

// ---------------- row norms ----------------
__global__ void k_norms(const float* __restrict__ ss, const float* __restrict__ sa,
                        const float* __restrict__ es, const float* __restrict__ ea) {
    int i = blockIdx.x * blockDim.x + threadIdx.x;
    if (i < NPTS) {
        float s = 0.f;
        #pragma unroll
        for (int k = 0; k < DS; k++) { float v = ss[(size_t)i * DS + k]; s += v * v; }
        #pragma unroll
        for (int k = 0; k < DA; k++) { float v = sa[(size_t)i * DA + k]; s += v * v; }
        g_x2[i] = s;
    } else if (i < 2 * NPTS) {
        int j = i - NPTS;
        float s = 0.f;
        #pragma unroll
        for (int k = 0; k < DS; k++) { float v = es[(size_t)j * DS + k]; s += v * v; }
        #pragma unroll
        for (int k = 0; k < DA; k++) { float v = ea[(size_t)j * DA + k]; s += v * v; }
        g_y2[j] = s;
    }
}

// ---------------- weight sums (double) ----------------
__global__ void k_wsum(const float* __restrict__ w, const float* __restrict__ ew) {
    __shared__ double sh[1024];
    int tid = threadIdx.x;
    double s1 = 0.0, s2 = 0.0;
    for (int i = tid; i < NPTS; i += 1024) { s1 += w[i]; s2 += ew[i]; }
    sh[tid] = s1; __syncthreads();
    for (int off = 512; off; off >>= 1) { if (tid < off) sh[tid] += sh[tid + off]; __syncthreads(); }
    if (tid == 0) g_scal[0] = sh[0];
    __syncthreads();
    sh[tid] = s2; __syncthreads();
    for (int off = 512; off; off >>= 1) { if (tid < off) sh[tid] += sh[tid + off]; __syncthreads(); }
    if (tid == 0) g_scal[1] = sh[0];
}

// ---------------- D_ae: GEMM-tile distance + store + SAMPLED coarse hist ----------------
__global__ void __launch_bounds__(256) k_dist_ae(
    const float* __restrict__ xs_s, const float* __restrict__ xs_a,
    const float* __restrict__ ys_s, const float* __restrict__ ys_a,
    const float* __restrict__ wxv, const float* __restrict__ wyv,
    float* __restrict__ Dout, float* __restrict__ hist)
{
    extern __shared__ float sm[];
    float* As   = sm;                  // DF*TB
    float* Bs   = As + DF * TB;        // DF*TB
    float* shh  = Bs + DF * TB;        // NB1
    float* shx2 = shh + NB1;           // TB
    float* shy2 = shx2 + TB;
    float* shwx = shy2 + TB;
    float* shwy = shwx + TB;

    int tid  = threadIdx.x;
    int row0 = blockIdx.y * TB;
    int col0 = blockIdx.x * TB;

    for (int i = tid; i < NB1; i += 256) shh[i] = 0.f;

    for (int e = tid; e < TB * DF; e += 256) {
        int r = e >> 6, k = e & 63;
        As[k * TB + r] = (k < DS) ? xs_s[(size_t)(row0 + r) * DS + k]
                                  : xs_a[(size_t)(row0 + r) * DA + (k - DS)];
        Bs[k * TB + r] = (k < DS) ? ys_s[(size_t)(col0 + r) * DS + k]
                                  : ys_a[(size_t)(col0 + r) * DA + (k - DS)];
    }
    if (tid < TB) {
        shx2[tid] = g_x2[row0 + tid];
        shy2[tid] = g_y2[col0 + tid];
        shwx[tid] = wxv[row0 + tid];
        shwy[tid] = wyv[col0 + tid];
    }
    __syncthreads();

    int tx = tid & 15, ty = tid >> 4;
    int ra = ty * 8, cb = tx * 8;

    float acc[8][8];
    #pragma unroll
    for (int r = 0; r < 8; r++)
        #pragma unroll
        for (int c = 0; c < 8; c++) acc[r][c] = 0.f;

    #pragma unroll 4
    for (int k = 0; k < DF; k++) {
        float a[8], b[8];
        *(float4*)&a[0] = *(const float4*)&As[k * TB + ra];
        *(float4*)&a[4] = *(const float4*)&As[k * TB + ra + 4];
        *(float4*)&b[0] = *(const float4*)&Bs[k * TB + cb];
        *(float4*)&b[4] = *(const float4*)&Bs[k * TB + cb + 4];
        #pragma unroll
        for (int r = 0; r < 8; r++)
            #pragma unroll
            for (int c = 0; c < 8; c++)
                acc[r][c] = fmaf(a[r], b[c], acc[r][c]);
    }

    #pragma unroll
    for (int r = 0; r < 8; r++) {
        int gr = row0 + ra + r;
        float x2r = shx2[ra + r];
        float wr  = shwx[ra + r];
        float d[8];
        #pragma unroll
        for (int c = 0; c < 8; c++)
            d[c] = fmaxf(x2r + shy2[cb + c] - 2.f * acc[r][c], 0.f) * (1.f / DF);
        float4* o = (float4*)&Dout[(size_t)gr * NPTS + col0 + cb];
        o[0] = make_float4(d[0], d[1], d[2], d[3]);
        o[1] = make_float4(d[4], d[5], d[6], d[7]);
        if (((ra + r) & 3) == 0) {   // sampled rows (stride 4)
            #pragma unroll
            for (int c = 0; c < 8; c += 4) {   // sampled cols (stride 4)
                int bb = (int)(d[c] * SC1);
                bb = bb > NB1 - 1 ? NB1 - 1 : bb;
                atomicAdd(&shh[bb], wr * shwy[cb + c]);
            }
        }
    }
    __syncthreads();
    for (int i = tid; i < NB1; i += 256) {
        float v = shh[i];
        if (v != 0.f) atomicAdd(&hist[i], v);
    }
}

// ---------------- D_ee: upper-triangle tiles only, store + sampled hist (2x weights) ----------------
__global__ void __launch_bounds__(256) k_dist_ee(
    const float* __restrict__ ys_s, const float* __restrict__ ys_a,
    const float* __restrict__ wyv,
    float* __restrict__ Dout, float* __restrict__ hist)
{
    extern __shared__ float sm[];
    float* As   = sm;
    float* Bs   = As + DF * TB;
    float* shh  = Bs + DF * TB;        // NB1
    float* shx2 = shh + NB1;
    float* shy2 = shx2 + TB;
    float* shwx = shy2 + TB;
    float* shwy = shwx + TB;

    int tid = threadIdx.x;
    int by = 0, t = blockIdx.x;
    while (t >= NTILE - by) { t -= NTILE - by; by++; }
    int bx = by + t;
    int row0 = by * TB, col0 = bx * TB;
    bool diag = (bx == by);

    for (int i = tid; i < NB1; i += 256) shh[i] = 0.f;

    for (int e = tid; e < TB * DF; e += 256) {
        int r = e >> 6, k = e & 63;
        As[k * TB + r] = (k < DS) ? ys_s[(size_t)(row0 + r) * DS + k]
                                  : ys_a[(size_t)(row0 + r) * DA + (k - DS)];
        Bs[k * TB + r] = (k < DS) ? ys_s[(size_t)(col0 + r) * DS + k]
                                  : ys_a[(size_t)(col0 + r) * DA + (k - DS)];
    }
    if (tid < TB) {
        shx2[tid] = g_y2[row0 + tid];
        shy2[tid] = g_y2[col0 + tid];
        shwx[tid] = wyv[row0 + tid];
        shwy[tid] = wyv[col0 + tid];
    }
    __syncthreads();

    int tx = tid & 15, ty = tid >> 4;
    int ra = ty * 8, cb = tx * 8;

    float acc[8][8];
    #pragma unroll
    for (int r = 0; r < 8; r++)
        #pragma unroll
        for (int c = 0; c < 8; c++) acc[r][c] = 0.f;

    #pragma unroll 4
    for (int k = 0; k < DF; k++) {
        float a[8], b[8];
        *(float4*)&a[0] = *(const float4*)&As[k * TB + ra];
        *(float4*)&a[4] = *(const float4*)&As[k * TB + ra + 4];
        *(float4*)&b[0] = *(const float4*)&Bs[k * TB + cb];
        *(float4*)&b[4] = *(const float4*)&Bs[k * TB + cb + 4];
        #pragma unroll
        for (int r = 0; r < 8; r++)
            #pragma unroll
            for (int c = 0; c < 8; c++)
                acc[r][c] = fmaf(a[r], b[c], acc[r][c]);
    }

    #pragma unroll
    for (int r = 0; r < 8; r++) {
        int gr = row0 + ra + r;
        float x2r = shx2[ra + r];
        float wr  = shwx[ra + r];
        float d[8];
        #pragma unroll
        for (int c = 0; c < 8; c++)
            d[c] = fmaxf(x2r + shy2[cb + c] - 2.f * acc[r][c], 0.f) * (1.f / DF);
        float4* o = (float4*)&Dout[(size_t)gr * NPTS + col0 + cb];
        o[0] = make_float4(d[0], d[1], d[2], d[3]);
        o[1] = make_float4(d[4], d[5], d[6], d[7]);
        if (((ra + r) & 3) == 0) {
            #pragma unroll
            for (int c = 0; c < 8; c += 4) {
                int gc = col0 + cb + c;
                float wfac = 2.f;
                if (diag) {
                    if (gc < gr) continue;
                    if (gc == gr) wfac = 1.f;
                }
                int bb = (int)(d[c] * SC1);
                bb = bb > NB1 - 1 ? NB1 - 1 : bb;
                atomicAdd(&shh[bb], wfac * wr * shwy[cb + c]);
            }
        }
    }
    __syncthreads();
    for (int i = tid; i < NB1; i += 256) {
        float v = shh[i];
        if (v != 0.f) atomicAdd(&hist[i], v);
    }
}

// ---------------- scan of sampled coarse hist -> window [lo, lo+width) ----------------
__global__ void k_scan0() {
    int which = blockIdx.x;              // 0 = ae, 1 = ee
    const float* h = g_hcoarse + which * NB1;
    __shared__ double part[256];
    int tid = threadIdx.x;
    double loc[8], s = 0.0;
    #pragma unroll
    for (int i = 0; i < 8; i++) { loc[i] = h[tid * 8 + i]; s += loc[i]; }
    part[tid] = s; __syncthreads();
    for (int off = 1; off < 256; off <<= 1) {
        double v = (tid >= off) ? part[tid - off] : 0.0;
        __syncthreads();
        part[tid] += v;
        __syncthreads();
    }
    double T = 0.5 * part[255];
    double c = tid ? part[tid - 1] : 0.0;
    int b = -1;
    #pragma unroll
    for (int i = 0; i < 8; i++) {
        double nc = c + loc[i];
        if (b < 0 && c < T && nc >= T) b = tid * 8 + i;
        c = nc;
    }
    if (b >= 0) {
        int blo = b > 4 ? b - 4 : 0;
        int bhi = b + 5 > NB1 ? NB1 : b + 5;
        g_scal[2 + 2 * which] = blo * (16.0 / NB1);
        g_scal[3 + 2 * which] = (bhi - blo) * (16.0 / NB1);
    }
}

// ---------------- refine pass over full (rect) D: exact below + fine hist in window ----------------
__global__ void k_refine_rect(const float* __restrict__ D, const float* __restrict__ wx,
                              const float* __restrict__ wy, int slot,
                              float* __restrict__ hist, double* __restrict__ below)
{
    __shared__ float shh[NBF];
    __shared__ double red[256];
    int tid = threadIdx.x;
    float lo    = (float)g_scal[slot];
    float scale = (float)((double)NBF / g_scal[slot + 1]);
    for (int i = tid; i < NBF; i += 256) shh[i] = 0.f;
    __syncthreads();
    size_t base = (size_t)blockIdx.x * 16384;
    float bacc = 0.f;
    for (int s = 0; s < 64; s++) {
        size_t idx = base + (size_t)s * 256 + tid;
        float v = D[idx];
        if (v < lo) {
            int i = (int)(idx >> 12), j = (int)(idx & 4095);
            bacc += wx[i] * wy[j];
        } else {
            int b = (int)((v - lo) * scale);   // float->int saturates, safe
            if (b < NBF) {
                int i = (int)(idx >> 12), j = (int)(idx & 4095);
                atomicAdd(&shh[b], wx[i] * wy[j]);
            }
        }
    }
    red[tid] = bacc; __syncthreads();
    for (int off = 128; off; off >>= 1) {
        if (tid < off) red[tid] += red[tid + off];
        __syncthreads();
    }
    if (tid == 0) atomicAdd(below, red[0]);
    for (int i = tid; i < NBF; i += 256) {
        float v = shh[i];
        if (v != 0.f) atomicAdd(&hist[i], v);
    }
}

// ---------------- refine pass over upper-tri D_ee (doubled weights) ----------------
__global__ void k_refine_tri(const float* __restrict__ D, const float* __restrict__ wv,
                             int slot, float* __restrict__ hist, double* __restrict__ below)
{
    __shared__ float shh[NBF];
    __shared__ double red[256];
    int tid = threadIdx.x;
    int by = 0, t = blockIdx.x;
    while (t >= NTILE - by) { t -= NTILE - by; by++; }
    int bx = by + t;
    int row0 = by * TB, col0 = bx * TB;
    bool diag = (bx == by);
    float lo    = (float)g_scal[slot];
    float scale = (float)((double)NBF / g_scal[slot + 1]);
    for (int i = tid; i < NBF; i += 256) shh[i] = 0.f;
    __syncthreads();
    float bacc = 0.f;
    for (int s = 0; s < 64; s++) {
        int e = s * 256 + tid;
        int r = e >> 7, c = e & 127;
        int gi = row0 + r, gj = col0 + c;
        if (diag && gj < gi) continue;
        float v = D[(size_t)gi * NPTS + gj];
        float wfac = (diag && gj == gi) ? 1.f : 2.f;
        if (v < lo) bacc += wfac * wv[gi] * wv[gj];
        else {
            int b = (int)((v - lo) * scale);
            if (b < NBF) atomicAdd(&shh[b], wfac * wv[gi] * wv[gj]);
        }
    }
    red[tid] = bacc; __syncthreads();
    for (int off = 128; off; off >>= 1) {
        if (tid < off) red[tid] += red[tid + off];
        __syncthreads();
    }
    if (tid == 0) atomicAdd(below, red[0]);
    for (int i = tid; i < NBF; i += 256) {
        float v = shh[i];
        if (v != 0.f) atomicAdd(&hist[i], v);
    }
}

// ---------------- scan fine hist; stage 0 -> narrow window, stage 1 -> final g ----------------
__global__ void k_scanF(int stage) {
    int which = blockIdx.x;
    const float* h = g_hfine + (stage * 2 + which) * NBF;
    __shared__ double part[1024];
    int tid = threadIdx.x;
    double loc[8], s = 0.0;
    #pragma unroll
    for (int i = 0; i < 8; i++) { loc[i] = h[tid * 8 + i]; s += loc[i]; }
    part[tid] = s; __syncthreads();
    for (int off = 1; off < 1024; off <<= 1) {
        double v = (tid >= off) ? part[tid - off] : 0.0;
        __syncthreads();
        part[tid] += v;
        __syncthreads();
    }
    double Wtot = (which == 0) ? g_scal[0] * g_scal[1] : g_scal[1] * g_scal[1];
    double T = 0.5 * Wtot - g_below[stage * 2 + which];
    double lo = g_scal[2 + 2 * which], wdt = g_scal[3 + 2 * which];
    double c = tid ? part[tid - 1] : 0.0;
    int b = -1;
    #pragma unroll
    for (int i = 0; i < 8; i++) {
        double nc = c + loc[i];
        if (b < 0 && c < T && nc >= T) b = tid * 8 + i;
        c = nc;
    }
    if (tid == 0 && T <= 0.0) b = 0;                                  // median below window (paranoia)
    if (tid == 1023 && T > 0.0 && part[1023] < T && b < 0) b = NBF - 1; // median above window (paranoia)
    if (b >= 0) {
        if (stage == 0) {
            g_scal[2 + 2 * which] = lo + b * (wdt / NBF);
            g_scal[3 + 2 * which] = wdt / NBF;
        } else {
            double tt = lo + (b + 0.5) * (wdt / NBF);
            g_scal[6 + which] = 1.0 / (tt + 1e-8);
        }
    }
}

// ---------------- kernel-sum over stored D_ae ----------------
__global__ void k_sumae(const float* __restrict__ ew) {
    int i = blockIdx.x;
    float G1 = (float)g_scal[6], G2 = (float)g_scal[7];
    const float* row = g_Dae + (size_t)i * NPTS;
    float s = 0.f;
    for (int j = threadIdx.x; j < NPTS; j += 256) {
        float dd = row[j];
        s += (__expf(-G1 * dd) + __expf(-G2 * dd)) * ew[j];
    }
    __shared__ float red[256];
    red[threadIdx.x] = s; __syncthreads();
    for (int off = 128; off; off >>= 1) {
        if (threadIdx.x < off) red[threadIdx.x] += red[threadIdx.x + off];
        __syncthreads();
    }
    if (threadIdx.x == 0) g_Sae[i] = red[0];
}

// ---------------- fused symmetric D_aa + kernel-sum (upper-tri tiles) ----------------
__global__ void __launch_bounds__(256) k_aa(
    const float* __restrict__ xs_s, const float* __restrict__ xs_a,
    const float* __restrict__ wv)
{
    extern __shared__ float sm[];
    float* As     = sm;
    float* Bs     = As + DF * TB;
    float* shx2   = Bs + DF * TB;
    float* shy2   = shx2 + TB;
    float* shwr   = shy2 + TB;
    float* shwc   = shwr + TB;
    float* rowsum = shwc + TB;
    float* colsum = rowsum + TB;

    int tid = threadIdx.x;
    int by = 0, t = blockIdx.x;
    while (t >= NTILE - by) { t -= NTILE - by; by++; }
    int bx = by + t;
    int row0 = by * TB, col0 = bx * TB;
    bool offd = (bx > by);

    if (tid < TB) { rowsum[tid] = 0.f; colsum[tid] = 0.f; }

    for (int e = tid; e < TB * DF; e += 256) {
        int r = e >> 6, k = e & 63;
        As[k * TB + r] = (k < DS) ? xs_s[(size_t)(row0 + r) * DS + k]
                                  : xs_a[(size_t)(row0 + r) * DA + (k - DS)];
        Bs[k * TB + r] = (k < DS) ? xs_s[(size_t)(col0 + r) * DS + k]
                                  : xs_a[(size_t)(col0 + r) * DA + (k - DS)];
    }
    if (tid < TB) {
        shx2[tid] = g_x2[row0 + tid];
        shy2[tid] = g_x2[col0 + tid];
        shwr[tid] = wv[row0 + tid];
        shwc[tid] = wv[col0 + tid];
    }
    __syncthreads();

    float G1 = (float)g_scal[6], G2 = (float)g_scal[7];

    int tx = tid & 15, ty = tid >> 4;
    int ra = ty * 8, cb = tx * 8;

    float acc[8][8];
    #pragma unroll
    for (int r = 0; r < 8; r++)
        #pragma unroll
        for (int c = 0; c < 8; c++) acc[r][c] = 0.f;

    #pragma unroll 4
    for (int k = 0; k < DF; k++) {
        float a[8], b[8];
        *(float4*)&a[0] = *(const float4*)&As[k * TB + ra];
        *(float4*)&a[4] = *(const float4*)&As[k * TB + ra + 4];
        *(float4*)&b[0] = *(const float4*)&Bs[k * TB + cb];
        *(float4*)&b[4] = *(const float4*)&Bs[k * TB + cb + 4];
        #pragma unroll
        for (int r = 0; r < 8; r++)
            #pragma unroll
            for (int c = 0; c < 8; c++)
                acc[r][c] = fmaf(a[r], b[c], acc[r][c]);
    }

    float cs[8];
    #pragma unroll
    for (int c = 0; c < 8; c++) cs[c] = 0.f;

    #pragma unroll
    for (int r = 0; r < 8; r++) {
        float x2r = shx2[ra + r];
        float wr  = shwr[ra + r];
        float rs = 0.f;
        #pragma unroll
        for (int c = 0; c < 8; c++) {
            float dd = fmaxf(x2r + shy2[cb + c] - 2.f * acc[r][c], 0.f) * (1.f / DF);
            float K = __expf(-G1 * dd) + __expf(-G2 * dd);
            rs += K * shwc[cb + c];
            cs[c] += K * wr;
        }
        atomicAdd(&rowsum[ra + r], rs);
    }
    if (offd) {
        #pragma unroll
        for (int c = 0; c < 8; c++) atomicAdd(&colsum[cb + c], cs[c]);
    }
    __syncthreads();
    if (tid < TB) {
        atomicAdd(&g_Saa[row0 + tid], rowsum[tid]);
        if (offd) atomicAdd(&g_Saa[col0 + tid], colsum[tid]);
    }
}

// ---------------- final combine ----------------
__global__ void k_combine(const float* __restrict__ w, float* __restrict__ out) {
    int i = blockIdx.x * blockDim.x + threadIdx.x;
    if (i < NPTS) {
        float Ws  = (float)g_scal[0];
        float EWs = (float)g_scal[1];
        out[i] = (w[i] / Ws) * (g_Sae[i] / EWs - g_Saa[i] / Ws);
    }
}

// ---------------- host launcher ----------------
extern "C" void kernel_launch(void* const* d_in, const int* in_sizes, int n_in,
                              void* d_out, int out_size)
{
    const float* state   = (const float*)d_in[0];
    const float* action  = (const float*)d_in[1];
    const float* estate  = (const float*)d_in[2];
    const float* eaction = (const float*)d_in[3];
    const float* w       = (const float*)d_in[4];
    const float* ew      = (const float*)d_in[5];
    float* out = (float*)d_out;

    const int SMEM_DIST = (DF * TB * 2 + NB1 + 4 * TB) * (int)sizeof(float);  // 75776
    const int SMEM_AA   = (DF * TB * 2 + 6 * TB) * (int)sizeof(float);        // 68608

    cudaFuncSetAttribute(k_dist_ae, cudaFuncAttributeMaxDynamicSharedMemorySize, SMEM_DIST);
    cudaFuncSetAttribute(k_dist_ee, cudaFuncAttributeMaxDynamicSharedMemorySize, SMEM_DIST);
    cudaFuncSetAttribute(k_aa,      cudaFuncAttributeMaxDynamicSharedMemorySize, SMEM_AA);

    float *p_hc, *p_hf, *p_Dae, *p_Dee;
    double* p_below;
    cudaGetSymbolAddress((void**)&p_hc,    g_hcoarse);
    cudaGetSymbolAddress((void**)&p_hf,    g_hfine);
    cudaGetSymbolAddress((void**)&p_Dae,   g_Dae);
    cudaGetSymbolAddress((void**)&p_Dee,   g_Dee);
    cudaGetSymbolAddress((void**)&p_below, g_below);

    dim3 grid(NTILE, NTILE);

    k_zero<<<128, 256>>>();
    k_norms<<<32, 256>>>(state, action, estate, eaction);
    k_wsum<<<1, 1024>>>(w, ew);

    k_dist_ae<<<grid, 256, SMEM_DIST>>>(state, action, estate, eaction,
                                        w, ew, p_Dae, p_hc);
    k_dist_ee<<<NTRI, 256, SMEM_DIST>>>(estate, eaction, ew, p_Dee, p_hc + NB1);

    k_scan0<<<2, 256>>>();

    // refine pass B: exact below-window mass + fine hist inside window
    k_refine_rect<<<1024, 256>>>(p_Dae, w, ew, 2, p_hf + 0 * NBF, p_below + 0);
    k_refine_tri<<<NTRI, 256>>>(p_Dee, ew, 4, p_hf + 1 * NBF, p_below + 1);
    k_scanF<<<2, 1024>>>(0);

    // refine pass C: ulp-exact median inside pass-B bin
    k_refine_rect<<<1024, 256>>>(p_Dae, w, ew, 2, p_hf + 2 * NBF, p_below + 2);
    k_refine_tri<<<NTRI, 256>>>(p_Dee, ew, 4, p_hf + 3 * NBF, p_below + 3);
    k_scanF<<<2, 1024>>>(1);

    k_sumae<<<NPTS, 256>>>(ew);
    k_aa<<<NTRI, 256, SMEM_AA>>>(state, action, w);

    k_combine<<<16, 256>>>(w, out);
}

// round 5
// speedup vs baseline: 1.4196x; 1.3844x over previous
#include <cuda_runtime.h>
#include <math.h>

#define NPTS 4096
#define DS 48
#define DA 16
#define DF 64
#define TB 128
#define NTILE (NPTS / TB)      /* 32 */
#define NTRI  528              /* upper-tri tiles */
#define NB1 2048               /* coarse bins over [0,16] */
#define SC1 128.0f             /* NB1/16 */
#define NBF 8192               /* fine bins per refine pass */

// ---------------- device scratch ----------------
__device__ float  g_Dae[(size_t)NPTS * NPTS];
__device__ float  g_Dee[(size_t)NPTS * NPTS];   // upper-tri tiles valid
__device__ float  g_x2[NPTS];
__device__ float  g_y2[NPTS];
__device__ float  g_hcoarse[2 * NB1];
__device__ float  g_hfine[4 * NBF];
__device__ double g_below[4];
__device__ double g_scal[8];   // 0 Wsum,1 EWsum,2/3 lo/width ae,4/5 lo/width ee,6 g1,7 g2
__device__ float  g_Sae[NPTS];
__device__ float  g_Saa[NPTS];

// ---------------- zero per-replay accumulators ----------------
__global__ void k_zero() {
    int i = blockIdx.x * blockDim.x + threadIdx.x;
    if (i < 2 * NB1)  g_hcoarse[i] = 0.f;
    if (i < 4 * NBF)  g_hfine[i]   = 0.f;
    if (i < NPTS)     g_Saa[i]     = 0.f;
    if (i < 4)        g_below[i]   = 0.0;
}

// ---------------- row norms ----------------
__global__ void k_norms(const float* __restrict__ ss, const float* __restrict__ sa,
                        const float* __restrict__ es, const float* __restrict__ ea) {
    int i = blockIdx.x * blockDim.x + threadIdx.x;
    if (i < NPTS) {
        float s = 0.f;
        #pragma unroll
        for (int k = 0; k < DS; k++) { float v = ss[(size_t)i * DS + k]; s += v * v; }
        #pragma unroll
        for (int k = 0; k < DA; k++) { float v = sa[(size_t)i * DA + k]; s += v * v; }
        g_x2[i] = s;
    } else if (i < 2 * NPTS) {
        int j = i - NPTS;
        float s = 0.f;
        #pragma unroll
        for (int k = 0; k < DS; k++) { float v = es[(size_t)j * DS + k]; s += v * v; }
        #pragma unroll
        for (int k = 0; k < DA; k++) { float v = ea[(size_t)j * DA + k]; s += v * v; }
        g_y2[j] = s;
    }
}

// ---------------- weight sums (double) ----------------
__global__ void k_wsum(const float* __restrict__ w, const float* __restrict__ ew) {
    __shared__ double sh[1024];
    int tid = threadIdx.x;
    double s1 = 0.0, s2 = 0.0;
    for (int i = tid; i < NPTS; i += 1024) { s1 += w[i]; s2 += ew[i]; }
    sh[tid] = s1; __syncthreads();
    for (int off = 512; off; off >>= 1) { if (tid < off) sh[tid] += sh[tid + off]; __syncthreads(); }
    if (tid == 0) g_scal[0] = sh[0];
    __syncthreads();
    sh[tid] = s2; __syncthreads();
    for (int off = 512; off; off >>= 1) { if (tid < off) sh[tid] += sh[tid + off]; __syncthreads(); }
    if (tid == 0) g_scal[1] = sh[0];
}

// ======== shared GEMM body: conflict-free 4+4 split micro-tile ========
// rows handled by thread: {ty*4+v, 64+ty*4+v}, cols: {tx*4+u, 64+tx*4+u}
// acc[r][c]: r 0-3 -> rowsA, 4-7 -> rowsB; c 0-3 -> colsA, 4-7 -> colsB.

// ---------------- D_ae: pure GEMM distance + store ----------------
__global__ void __launch_bounds__(256) k_dist_ae(
    const float* __restrict__ xs_s, const float* __restrict__ xs_a,
    const float* __restrict__ ys_s, const float* __restrict__ ys_a,
    float* __restrict__ Dout)
{
    extern __shared__ float sm[];
    float* As   = sm;                  // DF*TB
    float* Bs   = As + DF * TB;        // DF*TB
    float* shx2 = Bs + DF * TB;        // TB
    float* shy2 = shx2 + TB;

    int tid  = threadIdx.x;
    int row0 = blockIdx.y * TB;
    int col0 = blockIdx.x * TB;

    for (int e = tid; e < TB * DF; e += 256) {
        int r = e >> 6, k = e & 63;
        As[k * TB + r] = (k < DS) ? xs_s[(size_t)(row0 + r) * DS + k]
                                  : xs_a[(size_t)(row0 + r) * DA + (k - DS)];
        Bs[k * TB + r] = (k < DS) ? ys_s[(size_t)(col0 + r) * DS + k]
                                  : ys_a[(size_t)(col0 + r) * DA + (k - DS)];
    }
    if (tid < TB) {
        shx2[tid] = g_x2[row0 + tid];
        shy2[tid] = g_y2[col0 + tid];
    }
    __syncthreads();

    int tx = tid & 15, ty = tid >> 4;
    int ra = ty * 4, cb = tx * 4;

    float acc[8][8];
    #pragma unroll
    for (int r = 0; r < 8; r++)
        #pragma unroll
        for (int c = 0; c < 8; c++) acc[r][c] = 0.f;

    #pragma unroll 4
    for (int k = 0; k < DF; k++) {
        float a[8], b[8];
        *(float4*)&a[0] = *(const float4*)&As[k * TB + ra];
        *(float4*)&a[4] = *(const float4*)&As[k * TB + 64 + ra];
        *(float4*)&b[0] = *(const float4*)&Bs[k * TB + cb];
        *(float4*)&b[4] = *(const float4*)&Bs[k * TB + 64 + cb];
        #pragma unroll
        for (int r = 0; r < 8; r++)
            #pragma unroll
            for (int c = 0; c < 8; c++)
                acc[r][c] = fmaf(a[r], b[c], acc[r][c]);
    }

    #pragma unroll
    for (int r = 0; r < 8; r++) {
        int lr = (r < 4) ? (ra + r) : (64 + ra + r - 4);
        int gr = row0 + lr;
        float x2r = shx2[lr];
        float d[8];
        #pragma unroll
        for (int c = 0; c < 8; c++) {
            int lc = (c < 4) ? (cb + c) : (64 + cb + c - 4);
            d[c] = fmaxf(x2r + shy2[lc] - 2.f * acc[r][c], 0.f) * (1.f / DF);
        }
        float* orow = &Dout[(size_t)gr * NPTS + col0];
        *(float4*)&orow[cb]      = make_float4(d[0], d[1], d[2], d[3]);
        *(float4*)&orow[64 + cb] = make_float4(d[4], d[5], d[6], d[7]);
    }
}

// ---------------- D_ee: upper-tri tiles, pure GEMM + store ----------------
__global__ void __launch_bounds__(256) k_dist_ee(
    const float* __restrict__ ys_s, const float* __restrict__ ys_a,
    float* __restrict__ Dout)
{
    extern __shared__ float sm[];
    float* As   = sm;
    float* Bs   = As + DF * TB;
    float* shx2 = Bs + DF * TB;
    float* shy2 = shx2 + TB;

    int tid = threadIdx.x;
    int by = 0, t = blockIdx.x;
    while (t >= NTILE - by) { t -= NTILE - by; by++; }
    int bx = by + t;
    int row0 = by * TB, col0 = bx * TB;

    for (int e = tid; e < TB * DF; e += 256) {
        int r = e >> 6, k = e & 63;
        As[k * TB + r] = (k < DS) ? ys_s[(size_t)(row0 + r) * DS + k]
                                  : ys_a[(size_t)(row0 + r) * DA + (k - DS)];
        Bs[k * TB + r] = (k < DS) ? ys_s[(size_t)(col0 + r) * DS + k]
                                  : ys_a[(size_t)(col0 + r) * DA + (k - DS)];
    }
    if (tid < TB) {
        shx2[tid] = g_y2[row0 + tid];
        shy2[tid] = g_y2[col0 + tid];
    }
    __syncthreads();

    int tx = tid & 15, ty = tid >> 4;
    int ra = ty * 4, cb = tx * 4;

    float acc[8][8];
    #pragma unroll
    for (int r = 0; r < 8; r++)
        #pragma unroll
        for (int c = 0; c < 8; c++) acc[r][c] = 0.f;

    #pragma unroll 4
    for (int k = 0; k < DF; k++) {
        float a[8], b[8];
        *(float4*)&a[0] = *(const float4*)&As[k * TB + ra];
        *(float4*)&a[4] = *(const float4*)&As[k * TB + 64 + ra];
        *(float4*)&b[0] = *(const float4*)&Bs[k * TB + cb];
        *(float4*)&b[4] = *(const float4*)&Bs[k * TB + 64 + cb];
        #pragma unroll
        for (int r = 0; r < 8; r++)
            #pragma unroll
            for (int c = 0; c < 8; c++)
                acc[r][c] = fmaf(a[r], b[c], acc[r][c]);
    }

    #pragma unroll
    for (int r = 0; r < 8; r++) {
        int lr = (r < 4) ? (ra + r) : (64 + ra + r - 4);
        int gr = row0 + lr;
        float x2r = shx2[lr];
        float d[8];
        #pragma unroll
        for (int c = 0; c < 8; c++) {
            int lc = (c < 4) ? (cb + c) : (64 + cb + c - 4);
            d[c] = fmaxf(x2r + shy2[lc] - 2.f * acc[r][c], 0.f) * (1.f / DF);
        }
        float* orow = &Dout[(size_t)gr * NPTS + col0];
        *(float4*)&orow[cb]      = make_float4(d[0], d[1], d[2], d[3]);
        *(float4*)&orow[64 + cb] = make_float4(d[4], d[5], d[6], d[7]);
    }
}

// ---------------- sampled coarse histogram from stored D (1/16 of elements) ----------------
__global__ void k_hsamp_ae(const float* __restrict__ D, const float* __restrict__ wx,
                           const float* __restrict__ wy, float* __restrict__ hist)
{
    __shared__ float shh[NB1];
    int tid = threadIdx.x;
    for (int i = tid; i < NB1; i += 256) shh[i] = 0.f;
    __syncthreads();
    #pragma unroll
    for (int rr = 0; rr < 4; rr++) {
        int i = (blockIdx.x * 4 + rr) * 4;
        float wr = wx[i];
        const float* row = D + (size_t)i * NPTS;
        for (int jj = tid; jj < 1024; jj += 256) {
            int j = jj * 4;
            float v = row[j];
            int b = (int)(v * SC1);
            b = b > NB1 - 1 ? NB1 - 1 : b;
            atomicAdd(&shh[b], wr * wy[j]);
        }
    }
    __syncthreads();
    for (int i = tid; i < NB1; i += 256) {
        float v = shh[i];
        if (v != 0.f) atomicAdd(&hist[i], v);
    }
}

__global__ void k_hsamp_ee(const float* __restrict__ D, const float* __restrict__ wv,
                           float* __restrict__ hist)
{
    __shared__ float shh[NB1];
    int tid = threadIdx.x;
    for (int i = tid; i < NB1; i += 256) shh[i] = 0.f;
    __syncthreads();
    #pragma unroll
    for (int rr = 0; rr < 4; rr++) {
        int i = (blockIdx.x * 4 + rr) * 4;
        float wr = wv[i];
        const float* row = D + (size_t)i * NPTS;
        int cnt = (NPTS - i) / 4;              // j = i, i+4, ...
        for (int jj = tid; jj < cnt; jj += 256) {
            int j = i + jj * 4;
            float v = row[j];
            float wfac = (j == i) ? 1.f : 2.f;
            int b = (int)(v * SC1);
            b = b > NB1 - 1 ? NB1 - 1 : b;
            atomicAdd(&shh[b], wfac * wr * wv[j]);
        }
    }
    __syncthreads();
    for (int i = tid; i < NB1; i += 256) {
        float v = shh[i];
        if (v != 0.f) atomicAdd(&hist[i], v);
    }
}

// ---------------- scan of sampled coarse hist -> window ----------------
__global__ void k_scan0() {
    int which = blockIdx.x;
    const float* h = g_hcoarse + which * NB1;
    __shared__ double part[256];
    int tid = threadIdx.x;
    double loc[8], s = 0.0;
    #pragma unroll
    for (int i = 0; i < 8; i++) { loc[i] = h[tid * 8 + i]; s += loc[i]; }
    part[tid] = s; __syncthreads();
    for (int off = 1; off < 256; off <<= 1) {
        double v = (tid >= off) ? part[tid - off] : 0.0;
        __syncthreads();
        part[tid] += v;
        __syncthreads();
    }
    double T = 0.5 * part[255];
    double c = tid ? part[tid - 1] : 0.0;
    int b = -1;
    #pragma unroll
    for (int i = 0; i < 8; i++) {
        double nc = c + loc[i];
        if (b < 0 && c < T && nc >= T) b = tid * 8 + i;
        c = nc;
    }
    if (b >= 0) {
        int blo = b > 4 ? b - 4 : 0;
        int bhi = b + 5 > NB1 ? NB1 : b + 5;
        g_scal[2 + 2 * which] = blo * (16.0 / NB1);
        g_scal[3 + 2 * which] = (bhi - blo) * (16.0 / NB1);
    }
}

// ---------------- refine pass, rectangular D (float4) ----------------
__global__ void k_refine_rect(const float* __restrict__ D, const float* __restrict__ wx,
                              const float* __restrict__ wy, int slot,
                              float* __restrict__ hist, double* __restrict__ below)
{
    __shared__ float shh[NBF];
    __shared__ double red[256];
    int tid = threadIdx.x;
    float lo    = (float)g_scal[slot];
    float scale = (float)((double)NBF / g_scal[slot + 1]);
    for (int i = tid; i < NBF; i += 256) shh[i] = 0.f;
    __syncthreads();
    const float4* D4  = (const float4*)D;
    const float4* WY4 = (const float4*)wy;
    size_t base = (size_t)blockIdx.x * 4096;   // float4 index
    float bacc = 0.f;
    #pragma unroll 2
    for (int s = 0; s < 16; s++) {
        size_t idx = base + (size_t)s * 256 + tid;
        float4 v  = D4[idx];
        int i  = (int)(idx >> 10);
        int j4 = (int)(idx & 1023);
        float wi = wx[i];
        float4 wyv = WY4[j4];
        float vv[4] = {v.x, v.y, v.z, v.w};
        float ww[4] = {wyv.x, wyv.y, wyv.z, wyv.w};
        #pragma unroll
        for (int u = 0; u < 4; u++) {
            if (vv[u] < lo) bacc += wi * ww[u];
            else {
                int b = (int)((vv[u] - lo) * scale);
                if (b < NBF) atomicAdd(&shh[b], wi * ww[u]);
            }
        }
    }
    red[tid] = bacc; __syncthreads();
    for (int off = 128; off; off >>= 1) {
        if (tid < off) red[tid] += red[tid + off];
        __syncthreads();
    }
    if (tid == 0) atomicAdd(below, red[0]);
    for (int i = tid; i < NBF; i += 256) {
        float v = shh[i];
        if (v != 0.f) atomicAdd(&hist[i], v);
    }
}

// ---------------- refine pass, upper-tri D_ee (float4, doubled weights) ----------------
__global__ void k_refine_tri(const float* __restrict__ D, const float* __restrict__ wv,
                             int slot, float* __restrict__ hist, double* __restrict__ below)
{
    __shared__ float shh[NBF];
    __shared__ double red[256];
    int tid = threadIdx.x;
    int by = 0, t = blockIdx.x;
    while (t >= NTILE - by) { t -= NTILE - by; by++; }
    int bx = by + t;
    int row0 = by * TB, col0 = bx * TB;
    bool diag = (bx == by);
    float lo    = (float)g_scal[slot];
    float scale = (float)((double)NBF / g_scal[slot + 1]);
    for (int i = tid; i < NBF; i += 256) shh[i] = 0.f;
    __syncthreads();
    float bacc = 0.f;
    #pragma unroll 2
    for (int s = 0; s < 16; s++) {
        int e = s * 256 + tid;        // float4 element within 128x128 tile (32 f4/row)
        int r  = e >> 5;
        int c4 = e & 31;
        int gi = row0 + r;
        int gj0 = col0 + c4 * 4;
        if (diag && gj0 + 3 < gi) continue;
        float4 v = *(const float4*)&D[(size_t)gi * NPTS + gj0];
        float wi = wv[gi];
        float vv[4] = {v.x, v.y, v.z, v.w};
        #pragma unroll
        for (int u = 0; u < 4; u++) {
            int gj = gj0 + u;
            if (diag && gj < gi) continue;
            float wfac = (diag && gj == gi) ? 1.f : 2.f;
            float wt = wfac * wi * wv[gj];
            if (vv[u] < lo) bacc += wt;
            else {
                int b = (int)((vv[u] - lo) * scale);
                if (b < NBF) atomicAdd(&shh[b], wt);
            }
        }
    }
    red[tid] = bacc; __syncthreads();
    for (int off = 128; off; off >>= 1) {
        if (tid < off) red[tid] += red[tid + off];
        __syncthreads();
    }
    if (tid == 0) atomicAdd(below, red[0]);
    for (int i = tid; i < NBF; i += 256) {
        float v = shh[i];
        if (v != 0.f) atomicAdd(&hist[i], v);
    }
}

// ---------------- scan fine hist ----------------
__global__ void k_scanF(int stage) {
    int which = blockIdx.x;
    const float* h = g_hfine + (stage * 2 + which) * NBF;
    __shared__ double part[1024];
    int tid = threadIdx.x;
    double loc[8], s = 0.0;
    #pragma unroll
    for (int i = 0; i < 8; i++) { loc[i] = h[tid * 8 + i]; s += loc[i]; }
    part[tid] = s; __syncthreads();
    for (int off = 1; off < 1024; off <<= 1) {
        double v = (tid >= off) ? part[tid - off] : 0.0;
        __syncthreads();
        part[tid] += v;
        __syncthreads();
    }
    double Wtot = (which == 0) ? g_scal[0] * g_scal[1] : g_scal[1] * g_scal[1];
    double T = 0.5 * Wtot - g_below[stage * 2 + which];
    double lo = g_scal[2 + 2 * which], wdt = g_scal[3 + 2 * which];
    double c = tid ? part[tid - 1] : 0.0;
    int b = -1;
    #pragma unroll
    for (int i = 0; i < 8; i++) {
        double nc = c + loc[i];
        if (b < 0 && c < T && nc >= T) b = tid * 8 + i;
        c = nc;
    }
    if (tid == 0 && T <= 0.0) b = 0;
    if (tid == 1023 && T > 0.0 && part[1023] < T && b < 0) b = NBF - 1;
    if (b >= 0) {
        if (stage == 0) {
            g_scal[2 + 2 * which] = lo + b * (wdt / NBF);
            g_scal[3 + 2 * which] = wdt / NBF;
        } else {
            double tt = lo + (b + 0.5) * (wdt / NBF);
            g_scal[6 + which] = 1.0 / (tt + 1e-8);
        }
    }
}

// ---------------- kernel-sum over stored D_ae (float4) ----------------
__global__ void k_sumae(const float* __restrict__ ew) {
    int i = blockIdx.x;
    float G1 = (float)g_scal[6], G2 = (float)g_scal[7];
    const float4* row = (const float4*)(g_Dae + (size_t)i * NPTS);
    const float4* EW4 = (const float4*)ew;
    float s = 0.f;
    #pragma unroll 2
    for (int s4 = threadIdx.x; s4 < NPTS / 4; s4 += 256) {
        float4 d = row[s4];
        float4 e = EW4[s4];
        s += (__expf(-G1 * d.x) + __expf(-G2 * d.x)) * e.x;
        s += (__expf(-G1 * d.y) + __expf(-G2 * d.y)) * e.y;
        s += (__expf(-G1 * d.z) + __expf(-G2 * d.z)) * e.z;
        s += (__expf(-G1 * d.w) + __expf(-G2 * d.w)) * e.w;
    }
    __shared__ float red[256];
    red[threadIdx.x] = s; __syncthreads();
    for (int off = 128; off; off >>= 1) {
        if (threadIdx.x < off) red[threadIdx.x] += red[threadIdx.x + off];
        __syncthreads();
    }
    if (threadIdx.x == 0) g_Sae[i] = red[0];
}

// ---------------- fused symmetric D_aa + kernel-sum (upper-tri tiles) ----------------
__global__ void __launch_bounds__(256) k_aa(
    const float* __restrict__ xs_s, const float* __restrict__ xs_a,
    const float* __restrict__ wv)
{
    extern __shared__ float sm[];
    float* As     = sm;
    float* Bs     = As + DF * TB;
    float* shx2   = Bs + DF * TB;
    float* shy2   = shx2 + TB;
    float* shwr   = shy2 + TB;
    float* shwc   = shwr + TB;
    float* rowsum = shwc + TB;
    float* colsum = rowsum + TB;

    int tid = threadIdx.x;
    int by = 0, t = blockIdx.x;
    while (t >= NTILE - by) { t -= NTILE - by; by++; }
    int bx = by + t;
    int row0 = by * TB, col0 = bx * TB;
    bool offd = (bx > by);

    if (tid < TB) { rowsum[tid] = 0.f; colsum[tid] = 0.f; }

    for (int e = tid; e < TB * DF; e += 256) {
        int r = e >> 6, k = e & 63;
        As[k * TB + r] = (k < DS) ? xs_s[(size_t)(row0 + r) * DS + k]
                                  : xs_a[(size_t)(row0 + r) * DA + (k - DS)];
        Bs[k * TB + r] = (k < DS) ? xs_s[(size_t)(col0 + r) * DS + k]
                                  : xs_a[(size_t)(col0 + r) * DA + (k - DS)];
    }
    if (tid < TB) {
        shx2[tid] = g_x2[row0 + tid];
        shy2[tid] = g_x2[col0 + tid];
        shwr[tid] = wv[row0 + tid];
        shwc[tid] = wv[col0 + tid];
    }
    __syncthreads();

    float G1 = (float)g_scal[6], G2 = (float)g_scal[7];

    int tx = tid & 15, ty = tid >> 4;
    int ra = ty * 4, cb = tx * 4;

    float acc[8][8];
    #pragma unroll
    for (int r = 0; r < 8; r++)
        #pragma unroll
        for (int c = 0; c < 8; c++) acc[r][c] = 0.f;

    #pragma unroll 4
    for (int k = 0; k < DF; k++) {
        float a[8], b[8];
        *(float4*)&a[0] = *(const float4*)&As[k * TB + ra];
        *(float4*)&a[4] = *(const float4*)&As[k * TB + 64 + ra];
        *(float4*)&b[0] = *(const float4*)&Bs[k * TB + cb];
        *(float4*)&b[4] = *(const float4*)&Bs[k * TB + 64 + cb];
        #pragma unroll
        for (int r = 0; r < 8; r++)
            #pragma unroll
            for (int c = 0; c < 8; c++)
                acc[r][c] = fmaf(a[r], b[c], acc[r][c]);
    }

    float cs[8];
    #pragma unroll
    for (int c = 0; c < 8; c++) cs[c] = 0.f;

    #pragma unroll
    for (int r = 0; r < 8; r++) {
        int lr = (r < 4) ? (ra + r) : (64 + ra + r - 4);
        float x2r = shx2[lr];
        float wr  = shwr[lr];
        float rs = 0.f;
        #pragma unroll
        for (int c = 0; c < 8; c++) {
            int lc = (c < 4) ? (cb + c) : (64 + cb + c - 4);
            float dd = fmaxf(x2r + shy2[lc] - 2.f * acc[r][c], 0.f) * (1.f / DF);
            float K = __expf(-G1 * dd) + __expf(-G2 * dd);
            rs += K * shwc[lc];
            cs[c] += K * wr;
        }
        atomicAdd(&rowsum[lr], rs);
    }
    if (offd) {
        #pragma unroll
        for (int c = 0; c < 8; c++) {
            int lc = (c < 4) ? (cb + c) : (64 + cb + c - 4);
            atomicAdd(&colsum[lc], cs[c]);
        }
    }
    __syncthreads();
    if (tid < TB) {
        atomicAdd(&g_Saa[row0 + tid], rowsum[tid]);
        if (offd) atomicAdd(&g_Saa[col0 + tid], colsum[tid]);
    }
}

// ---------------- final combine ----------------
__global__ void k_combine(const float* __restrict__ w, float* __restrict__ out) {
    int i = blockIdx.x * blockDim.x + threadIdx.x;
    if (i < NPTS) {
        float Ws  = (float)g_scal[0];
        float EWs = (float)g_scal[1];
        out[i] = (w[i] / Ws) * (g_Sae[i] / EWs - g_Saa[i] / Ws);
    }
}

// ---------------- host launcher ----------------
extern "C" void kernel_launch(void* const* d_in, const int* in_sizes, int n_in,
                              void* d_out, int out_size)
{
    const float* state   = (const float*)d_in[0];
    const float* action  = (const float*)d_in[1];
    const float* estate  = (const float*)d_in[2];
    const float* eaction = (const float*)d_in[3];
    const float* w       = (const float*)d_in[4];
    const float* ew      = (const float*)d_in[5];
    float* out = (float*)d_out;

    const int SMEM_DIST = (DF * TB * 2 + 2 * TB) * (int)sizeof(float);   // 66560
    const int SMEM_AA   = (DF * TB * 2 + 6 * TB) * (int)sizeof(float);   // 68608

    cudaFuncSetAttribute(k_dist_ae, cudaFuncAttributeMaxDynamicSharedMemorySize, SMEM_DIST);
    cudaFuncSetAttribute(k_dist_ee, cudaFuncAttributeMaxDynamicSharedMemorySize, SMEM_DIST);
    cudaFuncSetAttribute(k_aa,      cudaFuncAttributeMaxDynamicSharedMemorySize, SMEM_AA);

    float *p_hc, *p_hf, *p_Dae, *p_Dee;
    double* p_below;
    cudaGetSymbolAddress((void**)&p_hc,    g_hcoarse);
    cudaGetSymbolAddress((void**)&p_hf,    g_hfine);
    cudaGetSymbolAddress((void**)&p_Dae,   g_Dae);
    cudaGetSymbolAddress((void**)&p_Dee,   g_Dee);
    cudaGetSymbolAddress((void**)&p_below, g_below);

    dim3 grid(NTILE, NTILE);

    k_zero<<<128, 256>>>();
    k_norms<<<32, 256>>>(state, action, estate, eaction);
    k_wsum<<<1, 1024>>>(w, ew);

    k_dist_ae<<<grid, 256, SMEM_DIST>>>(state, action, estate, eaction, p_Dae);
    k_dist_ee<<<NTRI, 256, SMEM_DIST>>>(estate, eaction, p_Dee);

    k_hsamp_ae<<<256, 256>>>(p_Dae, w, ew, p_hc);
    k_hsamp_ee<<<256, 256>>>(p_Dee, ew, p_hc + NB1);

    k_scan0<<<2, 256>>>();

    k_refine_rect<<<1024, 256>>>(p_Dae, w, ew, 2, p_hf + 0 * NBF, p_below + 0);
    k_refine_tri<<<NTRI, 256>>>(p_Dee, ew, 4, p_hf + 1 * NBF, p_below + 1);
    k_scanF<<<2, 1024>>>(0);

    k_refine_rect<<<1024, 256>>>(p_Dae, w, ew, 2, p_hf + 2 * NBF, p_below + 2);
    k_refine_tri<<<NTRI, 256>>>(p_Dee, ew, 4, p_hf + 3 * NBF, p_below + 3);
    k_scanF<<<2, 1024>>>(1);

    k_sumae<<<NPTS, 256>>>(ew);
    k_aa<<<NTRI, 256, SMEM_AA>>>(state, action, w);

    k_combine<<<16, 256>>>(w, out);
}

// round 7
// speedup vs baseline: 1.9692x; 1.3871x over previous
#include <cuda_runtime.h>
#include <cuda_bf16.h>
#include <math.h>
#include <stdint.h>

#define NPTS 4096
#define DS 48
#define DA 16
#define DF 64
#define TB 128
#define NTILE (NPTS / TB)      /* 32 */
#define NB1 2048               /* coarse bins over [0,16] */
#define SC1 128.0f             /* NB1/16 */
#define NBF 8192               /* fine bins in refine pass */
#define SP 72                  /* smem row stride in bf16 (144 B, conflict-free) */

// ---------------- device scratch ----------------
__device__ float  g_Dae[(size_t)NPTS * NPTS];
__device__ float  g_Dee[(size_t)NPTS * NPTS];
__device__ __nv_bfloat16 g_hiA[(size_t)NPTS * DF], g_loA[(size_t)NPTS * DF];
__device__ __nv_bfloat16 g_hiB[(size_t)NPTS * DF], g_loB[(size_t)NPTS * DF];
__device__ float  g_x2[NPTS];
__device__ float  g_y2[NPTS];
__device__ float  g_hcoarse[2 * NB1];
__device__ float  g_hfine[2 * NBF];
__device__ double g_below[2];
__device__ double g_scal[8];   // 0 Wsum,1 EWsum,2/3 lo/width ae,4/5 lo/width ee,6 g1,7 g2
__device__ float  g_Sae[NPTS];
__device__ float  g_Saa[NPTS];

// ---------------- mma.sync helper (sm_80+ PTX, works on compute_100) ----------------
#define MMA_BF16(d, a0, a1, a2, a3, b0, b1)                                 \
    asm volatile(                                                           \
        "mma.sync.aligned.m16n8k16.row.col.f32.bf16.bf16.f32 "              \
        "{%0,%1,%2,%3}, {%4,%5,%6,%7}, {%8,%9}, {%0,%1,%2,%3};"             \
        : "+f"((d)[0]), "+f"((d)[1]), "+f"((d)[2]), "+f"((d)[3])            \
        : "r"(a0), "r"(a1), "r"(a2), "r"(a3), "r"(b0), "r"(b1))

__device__ __forceinline__ uint32_t lds32(const char* p) {
    return *(const uint32_t*)p;
}

// SMEM layout for MMA kernels (dynamic)
#define OF_X2   0
#define OF_Y2   512
#define OF_W    1024
#define OF_RS   1536
#define OF_TILES 2048
#define TILE_BYTES (TB * SP * 2)            /* 18432 */
#define SMEM_MMA (OF_TILES + 4 * TILE_BYTES)  /* 75776 */

// ---------------- zero per-replay accumulators ----------------
__global__ void k_zero() {
    int i = blockIdx.x * blockDim.x + threadIdx.x;
    if (i < 2 * NB1) g_hcoarse[i] = 0.f;
    if (i < 2 * NBF) g_hfine[i]   = 0.f;
    if (i < NPTS)    g_Saa[i]     = 0.f;
    if (i < 2)       g_below[i]   = 0.0;
}

// ---------------- convert inputs to bf16 hi/lo + row norms ----------------
__global__ void k_cvt(const float* __restrict__ ss, const float* __restrict__ aa_,
                      const float* __restrict__ es, const float* __restrict__ ea) {
    int i = blockIdx.x * blockDim.x + threadIdx.x;
    if (i >= 2 * NPTS) return;
    bool isA = (i < NPTS);
    int r = isA ? i : i - NPTS;
    const float* sp = isA ? ss : es;
    const float* ap = isA ? aa_ : ea;
    __nv_bfloat16* hi = isA ? g_hiA : g_hiB;
    __nv_bfloat16* lo = isA ? g_loA : g_loB;
    float sum = 0.f;
    #pragma unroll
    for (int k = 0; k < DF; k++) {
        float v = (k < DS) ? sp[(size_t)r * DS + k] : ap[(size_t)r * DA + (k - DS)];
        sum += v * v;
        __nv_bfloat16 h = __float2bfloat16(v);
        float rem = v - __bfloat162float(h);
        hi[(size_t)r * DF + k] = h;
        lo[(size_t)r * DF + k] = __float2bfloat16(rem);
    }
    if (isA) g_x2[r] = sum; else g_y2[r] = sum;
}

// ---------------- weight sums (double) ----------------
__global__ void k_wsum(const float* __restrict__ w, const float* __restrict__ ew) {
    __shared__ double sh[1024];
    int tid = threadIdx.x;
    double s1 = 0.0, s2 = 0.0;
    for (int i = tid; i < NPTS; i += 1024) { s1 += w[i]; s2 += ew[i]; }
    sh[tid] = s1; __syncthreads();
    for (int off = 512; off; off >>= 1) { if (tid < off) sh[tid] += sh[tid + off]; __syncthreads(); }
    if (tid == 0) g_scal[0] = sh[0];
    __syncthreads();
    sh[tid] = s2; __syncthreads();
    for (int off = 512; off; off >>= 1) { if (tid < off) sh[tid] += sh[tid + off]; __syncthreads(); }
    if (tid == 0) g_scal[1] = sh[0];
}

// ======== shared mainloop: stage tiles + bf16 hi/lo 3-product mma ========
// warp grid 2x4 over 128x128 tile; warp tile 64 rows x 32 cols.
// acc[mf][nf][4] per thread: D[g][2t],D[g][2t+1],D[g+8][2t],D[g+8][2t+1]

__device__ __forceinline__ void stage_tiles(
    char* smem, int tid,
    const __nv_bfloat16* Ahi, const __nv_bfloat16* Alo, int row0,
    const __nv_bfloat16* Bhi, const __nv_bfloat16* Blo, int col0)
{
    const uint2* pAhi = (const uint2*)Ahi + (size_t)row0 * 16;
    const uint2* pAlo = (const uint2*)Alo + (size_t)row0 * 16;
    const uint2* pBhi = (const uint2*)Bhi + (size_t)col0 * 16;
    const uint2* pBlo = (const uint2*)Blo + (size_t)col0 * 16;
    char* sA = smem + OF_TILES;
    #pragma unroll 2
    for (int idx = tid; idx < 2048; idx += 256) {
        int r = idx >> 4, c8 = idx & 15;
        uint32_t off = (uint32_t)r * (SP * 2) + c8 * 8;
        *(uint2*)(sA + 0 * TILE_BYTES + off) = pAhi[idx];
        *(uint2*)(sA + 1 * TILE_BYTES + off) = pAlo[idx];
        *(uint2*)(sA + 2 * TILE_BYTES + off) = pBhi[idx];
        *(uint2*)(sA + 3 * TILE_BYTES + off) = pBlo[idx];
    }
}

__device__ __forceinline__ void mma_mainloop(char* smem, int tid, float acc[4][4][4]) {
    const int lane = tid & 31, warp = tid >> 5;
    const int wr = warp >> 2, wc = warp & 3;
    const int g = lane >> 2, t = lane & 3;
    const char* sAhi = smem + OF_TILES;
    const char* sAlo = sAhi + TILE_BYTES;
    const char* sBhi = sAlo + TILE_BYTES;
    const char* sBlo = sBhi + TILE_BYTES;

    #pragma unroll
    for (int mf = 0; mf < 4; mf++)
        #pragma unroll
        for (int nf = 0; nf < 4; nf++)
            #pragma unroll
            for (int u = 0; u < 4; u++) acc[mf][nf][u] = 0.f;

    #pragma unroll
    for (int ks = 0; ks < 4; ks++) {
        int kofs = ks * 32 + t * 4;                 // byte offset of element k=2t in this k-step
        uint32_t bh[4][2], bl[4][2];
        #pragma unroll
        for (int nf = 0; nf < 4; nf++) {
            uint32_t nro = (uint32_t)(wc * 32 + nf * 8 + g) * (SP * 2) + kofs;
            bh[nf][0] = lds32(sBhi + nro);
            bh[nf][1] = lds32(sBhi + nro + 16);
            bl[nf][0] = lds32(sBlo + nro);
            bl[nf][1] = lds32(sBlo + nro + 16);
        }
        #pragma unroll
        for (int mf = 0; mf < 4; mf++) {
            uint32_t aro = (uint32_t)(wr * 64 + mf * 16 + g) * (SP * 2) + kofs;
            uint32_t a0 = lds32(sAhi + aro);
            uint32_t a2 = lds32(sAhi + aro + 16);
            uint32_t a1 = lds32(sAhi + aro + 8 * (SP * 2));
            uint32_t a3 = lds32(sAhi + aro + 8 * (SP * 2) + 16);
            uint32_t l0 = lds32(sAlo + aro);
            uint32_t l2 = lds32(sAlo + aro + 16);
            uint32_t l1 = lds32(sAlo + aro + 8 * (SP * 2));
            uint32_t l3 = lds32(sAlo + aro + 8 * (SP * 2) + 16);
            #pragma unroll
            for (int nf = 0; nf < 4; nf++) {
                MMA_BF16(acc[mf][nf], a0, a1, a2, a3, bh[nf][0], bh[nf][1]);
                MMA_BF16(acc[mf][nf], a0, a1, a2, a3, bl[nf][0], bl[nf][1]);
                MMA_BF16(acc[mf][nf], l0, l1, l2, l3, bh[nf][0], bh[nf][1]);
            }
        }
    }
}

// ---------------- distance tile kernel: D = max(x2+y2-2*A.B^T,0)/64, store ----------------
__global__ void __launch_bounds__(256) k_mma_dist(
    const __nv_bfloat16* __restrict__ Ahi, const __nv_bfloat16* __restrict__ Alo,
    const __nv_bfloat16* __restrict__ Bhi, const __nv_bfloat16* __restrict__ Blo,
    const float* __restrict__ x2v, const float* __restrict__ y2v,
    float* __restrict__ Dout)
{
    extern __shared__ __align__(16) char smem[];
    int tid = threadIdx.x;
    int row0 = blockIdx.y * TB, col0 = blockIdx.x * TB;

    stage_tiles(smem, tid, Ahi, Alo, row0, Bhi, Blo, col0);
    if (tid < TB) {
        ((float*)(smem + OF_X2))[tid] = x2v[row0 + tid];
        ((float*)(smem + OF_Y2))[tid] = y2v[col0 + tid];
    }
    __syncthreads();

    float acc[4][4][4];
    mma_mainloop(smem, tid, acc);

    const int lane = tid & 31, warp = tid >> 5;
    const int wr = warp >> 2, wc = warp & 3;
    const int g = lane >> 2, t = lane & 3;
    const float* x2s = (const float*)(smem + OF_X2);
    const float* y2s = (const float*)(smem + OF_Y2);

    #pragma unroll
    for (int mf = 0; mf < 4; mf++) {
        int r0 = wr * 64 + mf * 16 + g;
        float x0 = x2s[r0], x1 = x2s[r0 + 8];
        #pragma unroll
        for (int nf = 0; nf < 4; nf++) {
            int c0 = wc * 32 + nf * 8 + 2 * t;
            float y0 = y2s[c0], y1 = y2s[c0 + 1];
            float2 o0, o1;
            o0.x = fmaxf(x0 + y0 - 2.f * acc[mf][nf][0], 0.f) * (1.f / DF);
            o0.y = fmaxf(x0 + y1 - 2.f * acc[mf][nf][1], 0.f) * (1.f / DF);
            o1.x = fmaxf(x1 + y0 - 2.f * acc[mf][nf][2], 0.f) * (1.f / DF);
            o1.y = fmaxf(x1 + y1 - 2.f * acc[mf][nf][3], 0.f) * (1.f / DF);
            *(float2*)&Dout[(size_t)(row0 + r0) * NPTS + col0 + c0] = o0;
            *(float2*)&Dout[(size_t)(row0 + r0 + 8) * NPTS + col0 + c0] = o1;
        }
    }
}

// ---------------- D_aa tile + fused exp row-sum (no store) ----------------
__global__ void __launch_bounds__(256) k_mma_aa(
    const __nv_bfloat16* __restrict__ Ahi, const __nv_bfloat16* __restrict__ Alo,
    const float* __restrict__ x2v, const float* __restrict__ wv)
{
    extern __shared__ __align__(16) char smem[];
    int tid = threadIdx.x;
    int row0 = blockIdx.y * TB, col0 = blockIdx.x * TB;

    stage_tiles(smem, tid, Ahi, Alo, row0, Ahi, Alo, col0);
    if (tid < TB) {
        ((float*)(smem + OF_X2))[tid] = x2v[row0 + tid];
        ((float*)(smem + OF_Y2))[tid] = x2v[col0 + tid];
        ((float*)(smem + OF_W))[tid]  = wv[col0 + tid];
        ((float*)(smem + OF_RS))[tid] = 0.f;
    }
    __syncthreads();

    float acc[4][4][4];
    mma_mainloop(smem, tid, acc);

    const int lane = tid & 31, warp = tid >> 5;
    const int wr = warp >> 2, wc = warp & 3;
    const int g = lane >> 2, t = lane & 3;
    const float* x2s = (const float*)(smem + OF_X2);
    const float* y2s = (const float*)(smem + OF_Y2);
    const float* ws  = (const float*)(smem + OF_W);
    float* rowsum = (float*)(smem + OF_RS);

    float G1 = (float)g_scal[6], G2 = (float)g_scal[7];

    #pragma unroll
    for (int mf = 0; mf < 4; mf++) {
        int r0 = wr * 64 + mf * 16 + g;
        float x0 = x2s[r0], x1 = x2s[r0 + 8];
        float p0 = 0.f, p1 = 0.f;
        #pragma unroll
        for (int nf = 0; nf < 4; nf++) {
            int c0 = wc * 32 + nf * 8 + 2 * t;
            float y0 = y2s[c0], y1 = y2s[c0 + 1];
            float w0 = ws[c0],  w1 = ws[c0 + 1];
            float d00 = fmaxf(x0 + y0 - 2.f * acc[mf][nf][0], 0.f) * (1.f / DF);
            float d01 = fmaxf(x0 + y1 - 2.f * acc[mf][nf][1], 0.f) * (1.f / DF);
            float d10 = fmaxf(x1 + y0 - 2.f * acc[mf][nf][2], 0.f) * (1.f / DF);
            float d11 = fmaxf(x1 + y1 - 2.f * acc[mf][nf][3], 0.f) * (1.f / DF);
            p0 += (__expf(-G1 * d00) + __expf(-G2 * d00)) * w0
                + (__expf(-G1 * d01) + __expf(-G2 * d01)) * w1;
            p1 += (__expf(-G1 * d10) + __expf(-G2 * d10)) * w0
                + (__expf(-G1 * d11) + __expf(-G2 * d11)) * w1;
        }
        atomicAdd(&rowsum[r0], p0);
        atomicAdd(&rowsum[r0 + 8], p1);
    }
    __syncthreads();
    if (tid < TB) atomicAdd(&g_Saa[row0 + tid], rowsum[tid]);
}

// ---------------- coarse histogram: every 8th row, full row, coalesced ----------------
__global__ void k_hsamp(const float* __restrict__ D, const float* __restrict__ wx,
                        const float* __restrict__ wy, float* __restrict__ hist)
{
    __shared__ float shh[NB1];
    int tid = threadIdx.x;
    for (int i = tid; i < NB1; i += 256) shh[i] = 0.f;
    __syncthreads();
    const float4* WY4 = (const float4*)wy;
    #pragma unroll
    for (int rr = 0; rr < 4; rr++) {
        int i = (blockIdx.x * 4 + rr) * 8;
        float wr = wx[i];
        const float4* row = (const float4*)(D + (size_t)i * NPTS);
        for (int j4 = tid; j4 < NPTS / 4; j4 += 256) {
            float4 v = row[j4];
            float4 wv4 = WY4[j4];
            float vv[4] = {v.x, v.y, v.z, v.w};
            float ww[4] = {wv4.x, wv4.y, wv4.z, wv4.w};
            #pragma unroll
            for (int u = 0; u < 4; u++) {
                int b = (int)(vv[u] * SC1);
                b = b > NB1 - 1 ? NB1 - 1 : b;
                atomicAdd(&shh[b], wr * ww[u]);
            }
        }
    }
    __syncthreads();
    for (int i = tid; i < NB1; i += 256) {
        float v = shh[i];
        if (v != 0.f) atomicAdd(&hist[i], v);
    }
}

// ---------------- scan coarse hist -> window (±16 bins) ----------------
__global__ void k_scan0() {
    int which = blockIdx.x;
    const float* h = g_hcoarse + which * NB1;
    __shared__ double part[256];
    int tid = threadIdx.x;
    double loc[8], s = 0.0;
    #pragma unroll
    for (int i = 0; i < 8; i++) { loc[i] = h[tid * 8 + i]; s += loc[i]; }
    part[tid] = s; __syncthreads();
    for (int off = 1; off < 256; off <<= 1) {
        double v = (tid >= off) ? part[tid - off] : 0.0;
        __syncthreads();
        part[tid] += v;
        __syncthreads();
    }
    double T = 0.5 * part[255];
    double c = tid ? part[tid - 1] : 0.0;
    int b = -1;
    #pragma unroll
    for (int i = 0; i < 8; i++) {
        double nc = c + loc[i];
        if (b < 0 && c < T && nc >= T) b = tid * 8 + i;
        c = nc;
    }
    if (b >= 0) {
        int blo = b > 16 ? b - 16 : 0;
        int bhi = b + 17 > NB1 ? NB1 : b + 17;
        g_scal[2 + 2 * which] = blo * (16.0 / NB1);
        g_scal[3 + 2 * which] = (bhi - blo) * (16.0 / NB1);
    }
}

// ---------------- refine pass: exact below-window mass + fine hist in window ----------------
__global__ void k_refine(const float* __restrict__ D, const float* __restrict__ wx,
                         const float* __restrict__ wy, int slot,
                         float* __restrict__ hist, double* __restrict__ below)
{
    __shared__ float shh[NBF];
    __shared__ double red[256];
    int tid = threadIdx.x;
    float lo    = (float)g_scal[slot];
    float scale = (float)((double)NBF / g_scal[slot + 1]);
    for (int i = tid; i < NBF; i += 256) shh[i] = 0.f;
    __syncthreads();
    const float4* D4  = (const float4*)D;
    const float4* WY4 = (const float4*)wy;
    size_t base = (size_t)blockIdx.x * 4096;
    float bacc = 0.f;
    #pragma unroll 2
    for (int s = 0; s < 16; s++) {
        size_t idx = base + (size_t)s * 256 + tid;
        float4 v = D4[idx];
        int i  = (int)(idx >> 10);
        int j4 = (int)(idx & 1023);
        float wi = wx[i];
        float4 wv4 = WY4[j4];
        float vv[4] = {v.x, v.y, v.z, v.w};
        float ww[4] = {wv4.x, wv4.y, wv4.z, wv4.w};
        #pragma unroll
        for (int u = 0; u < 4; u++) {
            if (vv[u] < lo) bacc += wi * ww[u];
            else {
                int b = (int)((vv[u] - lo) * scale);
                if (b < NBF) atomicAdd(&shh[b], wi * ww[u]);
            }
        }
    }
    red[tid] = bacc; __syncthreads();
    for (int off = 128; off; off >>= 1) {
        if (tid < off) red[tid] += red[tid + off];
        __syncthreads();
    }
    if (tid == 0) atomicAdd(below, red[0]);
    for (int i = tid; i < NBF; i += 256) {
        float v = shh[i];
        if (v != 0.f) atomicAdd(&hist[i], v);
    }
}

// ---------------- scan fine hist -> g ----------------
__global__ void k_scanF() {
    int which = blockIdx.x;
    const float* h = g_hfine + which * NBF;
    __shared__ double part[1024];
    int tid = threadIdx.x;
    double loc[8], s = 0.0;
    #pragma unroll
    for (int i = 0; i < 8; i++) { loc[i] = h[tid * 8 + i]; s += loc[i]; }
    part[tid] = s; __syncthreads();
    for (int off = 1; off < 1024; off <<= 1) {
        double v = (tid >= off) ? part[tid - off] : 0.0;
        __syncthreads();
        part[tid] += v;
        __syncthreads();
    }
    double Wtot = (which == 0) ? g_scal[0] * g_scal[1] : g_scal[1] * g_scal[1];
    double T = 0.5 * Wtot - g_below[which];
    double lo = g_scal[2 + 2 * which], wdt = g_scal[3 + 2 * which];
    double c = tid ? part[tid - 1] : 0.0;
    int b = -1;
    #pragma unroll
    for (int i = 0; i < 8; i++) {
        double nc = c + loc[i];
        if (b < 0 && c < T && nc >= T) b = tid * 8 + i;
        c = nc;
    }
    if (tid == 0 && T <= 0.0) b = 0;
    if (tid == 1023 && T > 0.0 && part[1023] < T && b < 0) b = NBF - 1;
    if (b >= 0) {
        double tt = lo + (b + 0.5) * (wdt / NBF);
        g_scal[6 + which] = 1.0 / (tt + 1e-8);
    }
}

// ---------------- kernel-sum over stored D_ae ----------------
__global__ void k_sumae(const float* __restrict__ ew) {
    int i = blockIdx.x;
    float G1 = (float)g_scal[6], G2 = (float)g_scal[7];
    const float4* row = (const float4*)(g_Dae + (size_t)i * NPTS);
    const float4* EW4 = (const float4*)ew;
    float s = 0.f;
    #pragma unroll 2
    for (int s4 = threadIdx.x; s4 < NPTS / 4; s4 += 256) {
        float4 d = row[s4];
        float4 e = EW4[s4];
        s += (__expf(-G1 * d.x) + __expf(-G2 * d.x)) * e.x;
        s += (__expf(-G1 * d.y) + __expf(-G2 * d.y)) * e.y;
        s += (__expf(-G1 * d.z) + __expf(-G2 * d.z)) * e.z;
        s += (__expf(-G1 * d.w) + __expf(-G2 * d.w)) * e.w;
    }
    __shared__ float red[256];
    red[threadIdx.x] = s; __syncthreads();
    for (int off = 128; off; off >>= 1) {
        if (threadIdx.x < off) red[threadIdx.x] += red[threadIdx.x + off];
        __syncthreads();
    }
    if (threadIdx.x == 0) g_Sae[i] = red[0];
}

// ---------------- final combine ----------------
__global__ void k_combine(const float* __restrict__ w, float* __restrict__ out) {
    int i = blockIdx.x * blockDim.x + threadIdx.x;
    if (i < NPTS) {
        float Ws  = (float)g_scal[0];
        float EWs = (float)g_scal[1];
        out[i] = (w[i] / Ws) * (g_Sae[i] / EWs - g_Saa[i] / Ws);
    }
}

// ---------------- host launcher ----------------
extern "C" void kernel_launch(void* const* d_in, const int* in_sizes, int n_in,
                              void* d_out, int out_size)
{
    const float* state   = (const float*)d_in[0];
    const float* action  = (const float*)d_in[1];
    const float* estate  = (const float*)d_in[2];
    const float* eaction = (const float*)d_in[3];
    const float* w       = (const float*)d_in[4];
    const float* ew      = (const float*)d_in[5];
    float* out = (float*)d_out;

    cudaFuncSetAttribute(k_mma_dist, cudaFuncAttributeMaxDynamicSharedMemorySize, SMEM_MMA);
    cudaFuncSetAttribute(k_mma_aa,   cudaFuncAttributeMaxDynamicSharedMemorySize, SMEM_MMA);

    float *p_hc, *p_hf, *p_Dae, *p_Dee, *p_x2, *p_y2;
    __nv_bfloat16 *p_hiA, *p_loA, *p_hiB, *p_loB;
    double* p_below;
    cudaGetSymbolAddress((void**)&p_hc,    g_hcoarse);
    cudaGetSymbolAddress((void**)&p_hf,    g_hfine);
    cudaGetSymbolAddress((void**)&p_Dae,   g_Dae);
    cudaGetSymbolAddress((void**)&p_Dee,   g_Dee);
    cudaGetSymbolAddress((void**)&p_x2,    g_x2);
    cudaGetSymbolAddress((void**)&p_y2,    g_y2);
    cudaGetSymbolAddress((void**)&p_hiA,   g_hiA);
    cudaGetSymbolAddress((void**)&p_loA,   g_loA);
    cudaGetSymbolAddress((void**)&p_hiB,   g_hiB);
    cudaGetSymbolAddress((void**)&p_loB,   g_loB);
    cudaGetSymbolAddress((void**)&p_below, g_below);

    dim3 g32(NTILE, NTILE);

    k_zero<<<128, 256>>>();
    k_cvt<<<32, 256>>>(state, action, estate, eaction);
    k_wsum<<<1, 1024>>>(w, ew);

    k_mma_dist<<<g32, 256, SMEM_MMA>>>(p_hiA, p_loA, p_hiB, p_loB, p_x2, p_y2, p_Dae);
    k_mma_dist<<<g32, 256, SMEM_MMA>>>(p_hiB, p_loB, p_hiB, p_loB, p_y2, p_y2, p_Dee);

    k_hsamp<<<128, 256>>>(p_Dae, w,  ew, p_hc);
    k_hsamp<<<128, 256>>>(p_Dee, ew, ew, p_hc + NB1);

    k_scan0<<<2, 256>>>();

    k_refine<<<1024, 256>>>(p_Dae, w,  ew, 2, p_hf + 0 * NBF, p_below + 0);
    k_refine<<<1024, 256>>>(p_Dee, ew, ew, 4, p_hf + 1 * NBF, p_below + 1);

    k_scanF<<<2, 1024>>>();

    k_sumae<<<NPTS, 256>>>(ew);
    k_mma_aa<<<g32, 256, SMEM_MMA>>>(p_hiA, p_loA, p_x2, w);

    k_combine<<<16, 256>>>(w, out);
}

// round 8
// speedup vs baseline: 2.5750x; 1.3077x over previous
#include <cuda_runtime.h>
#include <cuda_bf16.h>
#include <math.h>
#include <stdint.h>

#define NPTS 4096
#define DS 48
#define DA 16
#define DF 64
#define TB 128
#define NTILE (NPTS / TB)      /* 32 */
#define NB1 2048               /* coarse bins over [0,16] */
#define SC1 128.0f             /* NB1/16 */
#define NBF 8192               /* fine bins in refine pass */

// ---------------- device scratch ----------------
__device__ float  g_Dae[(size_t)NPTS * NPTS];
__device__ float  g_Dee[(size_t)NPTS * NPTS];
__device__ __nv_bfloat16 g_hiA[(size_t)NPTS * DF], g_loA[(size_t)NPTS * DF];
__device__ __nv_bfloat16 g_hiB[(size_t)NPTS * DF], g_loB[(size_t)NPTS * DF];
__device__ float  g_x2[NPTS];
__device__ float  g_y2[NPTS];
__device__ float  g_hcoarse[2 * NB1];
__device__ float  g_hfine[2 * NBF];
__device__ double g_below[2];
__device__ double g_scal[8];   // 0 Wsum,1 EWsum,2/3 lo/width ae,4/5 lo/width ee,6 g1,7 g2
__device__ float  g_Sae[NPTS];
__device__ float  g_Saa[NPTS];

// ---------------- mma / ldmatrix helpers ----------------
#define MMA_AB(d, A, b0, b1)                                                \
    asm volatile(                                                           \
        "mma.sync.aligned.m16n8k16.row.col.f32.bf16.bf16.f32 "              \
        "{%0,%1,%2,%3}, {%4,%5,%6,%7}, {%8,%9}, {%0,%1,%2,%3};"             \
        : "+f"((d)[0]), "+f"((d)[1]), "+f"((d)[2]), "+f"((d)[3])            \
        : "r"((A)[0]), "r"((A)[1]), "r"((A)[2]), "r"((A)[3]), "r"(b0), "r"(b1))

__device__ __forceinline__ void ldsm4(uint32_t a, uint32_t d[4]) {
    asm volatile("ldmatrix.sync.aligned.m8n8.x4.shared.b16 {%0,%1,%2,%3}, [%4];"
                 : "=r"(d[0]), "=r"(d[1]), "=r"(d[2]), "=r"(d[3]) : "r"(a));
}

// swizzled offset within a 128x(64 bf16) tile: 128-byte rows, XOR on 16B units
#define SWO(r, kc) ((uint32_t)(r) * 128u + (((uint32_t)(kc)) ^ (((uint32_t)(r) & 7u) << 4)))

// SMEM layout (dist kernel; final kernel uses subset)
#define OF_X2    0
#define OF_Y2    512
#define OF_WX    1024
#define OF_WY    1536
#define OF_HIST  2048                 /* NB1*4 = 8192 */
#define OF_TILES 10240                /* 128-byte aligned */
#define TILE_BYTES 16384
#define SMEM_DIST (OF_TILES + 4 * TILE_BYTES)   /* 75776 */

#define FOF_X2    0
#define FOF_Y2    512
#define FOF_W     1024
#define FOF_RS    1536
#define FOF_TILES 2048
#define SMEM_FIN (FOF_TILES + 4 * TILE_BYTES)   /* 67584 */

// ---------------- zero per-replay accumulators ----------------
__global__ void k_zero() {
    int i = blockIdx.x * blockDim.x + threadIdx.x;
    if (i < 2 * NB1) g_hcoarse[i] = 0.f;
    if (i < 2 * NBF) g_hfine[i]   = 0.f;
    if (i < NPTS)  { g_Saa[i] = 0.f; g_Sae[i] = 0.f; }
    if (i < 2)       g_below[i]   = 0.0;
}

// ---------------- convert inputs to bf16 hi/lo + row norms (coalesced) ----------------
__global__ void k_cvt(const float* __restrict__ ss, const float* __restrict__ aa_,
                      const float* __restrict__ es, const float* __restrict__ ea) {
    __shared__ float part[8];
    int tid = threadIdx.x;
    int gr = blockIdx.x * 4 + (tid >> 6);       // 0..8191
    int k  = tid & 63;
    bool isA = (gr < NPTS);
    int r = isA ? gr : gr - NPTS;
    const float* sp = isA ? ss : es;
    const float* ap = isA ? aa_ : ea;
    __nv_bfloat16* hi = isA ? g_hiA : g_hiB;
    __nv_bfloat16* lo = isA ? g_loA : g_loB;

    float v = (k < DS) ? sp[(size_t)r * DS + k] : ap[(size_t)r * DA + (k - DS)];
    __nv_bfloat16 h = __float2bfloat16(v);
    hi[(size_t)r * DF + k] = h;
    lo[(size_t)r * DF + k] = __float2bfloat16(v - __bfloat162float(h));

    // norm: reduce v*v over 64 threads (2 warps)
    float sq = v * v;
    #pragma unroll
    for (int off = 16; off; off >>= 1) sq += __shfl_xor_sync(0xFFFFFFFF, sq, off);
    if ((tid & 31) == 0) part[tid >> 5] = sq;
    __syncthreads();
    if ((tid & 63) == 0) {
        float s = part[(tid >> 5)] + part[(tid >> 5) + 1];
        if (isA) g_x2[r] = s; else g_y2[r] = s;
    }
}

// ---------------- weight sums (double) ----------------
__global__ void k_wsum(const float* __restrict__ w, const float* __restrict__ ew) {
    __shared__ double sh[1024];
    int tid = threadIdx.x;
    double s1 = 0.0, s2 = 0.0;
    for (int i = tid; i < NPTS; i += 1024) { s1 += w[i]; s2 += ew[i]; }
    sh[tid] = s1; __syncthreads();
    for (int off = 512; off; off >>= 1) { if (tid < off) sh[tid] += sh[tid + off]; __syncthreads(); }
    if (tid == 0) g_scal[0] = sh[0];
    __syncthreads();
    sh[tid] = s2; __syncthreads();
    for (int off = 512; off; off >>= 1) { if (tid < off) sh[tid] += sh[tid + off]; __syncthreads(); }
    if (tid == 0) g_scal[1] = sh[0];
}

// ======== staging: global (row-major 128B rows) -> swizzled smem ========
__device__ __forceinline__ void stage_tiles(
    char* smem, uint32_t tilesOff, int tid,
    const __nv_bfloat16* Ahi, const __nv_bfloat16* Alo, int row0,
    const __nv_bfloat16* Bhi, const __nv_bfloat16* Blo, int col0)
{
    const uint4* pAhi = (const uint4*)Ahi + (size_t)row0 * 8;
    const uint4* pAlo = (const uint4*)Alo + (size_t)row0 * 8;
    const uint4* pBhi = (const uint4*)Bhi + (size_t)col0 * 8;
    const uint4* pBlo = (const uint4*)Blo + (size_t)col0 * 8;
    char* sT = smem + tilesOff;
    #pragma unroll
    for (int idx = tid; idx < 1024; idx += 256) {
        int r = idx >> 3, c = idx & 7;
        uint32_t off = (uint32_t)r * 128u + (((uint32_t)c * 16u) ^ (((uint32_t)r & 7u) << 4));
        *(uint4*)(sT + 0 * TILE_BYTES + off) = pAhi[idx];
        *(uint4*)(sT + 1 * TILE_BYTES + off) = pAlo[idx];
        *(uint4*)(sT + 2 * TILE_BYTES + off) = pBhi[idx];
        *(uint4*)(sT + 3 * TILE_BYTES + off) = pBlo[idx];
    }
}

// ======== mainloop: ldmatrix.x4 + bf16 hi/lo 3-product mma ========
// warp grid 2x4 over 128x128 tile; warp tile 64 rows x 32 cols.
__device__ __forceinline__ void mma_mainloop(uint32_t sT, int tid, float acc[4][4][4]) {
    const int lane = tid & 31, warp = tid >> 5;
    const int wr = warp >> 2, wc = warp & 3;

    #pragma unroll
    for (int mf = 0; mf < 4; mf++)
        #pragma unroll
        for (int nf = 0; nf < 4; nf++)
            #pragma unroll
            for (int u = 0; u < 4; u++) acc[mf][nf][u] = 0.f;

    const int aRow = lane & 15;
    const int aKc  = (lane >> 4) << 4;                  // 0 or 16
    const int bRow = ((lane & 16) >> 1) + (lane & 7);   // 0..15
    const int bKc  = (lane & 8) ? 16 : 0;

    #pragma unroll
    for (int ks = 0; ks < 4; ks++) {
        const int kc0 = ks * 32;
        uint32_t BH[2][4], BL[2][4];
        #pragma unroll
        for (int p = 0; p < 2; p++) {
            uint32_t off = SWO(wc * 32 + p * 16 + bRow, kc0 + bKc);
            ldsm4(sT + 2 * TILE_BYTES + off, BH[p]);
            ldsm4(sT + 3 * TILE_BYTES + off, BL[p]);
        }
        #pragma unroll
        for (int mf = 0; mf < 4; mf++) {
            uint32_t off = SWO(wr * 64 + mf * 16 + aRow, kc0 + aKc);
            uint32_t AH[4], AL[4];
            ldsm4(sT + off, AH);
            ldsm4(sT + TILE_BYTES + off, AL);
            #pragma unroll
            for (int p = 0; p < 2; p++) {
                MMA_AB(acc[mf][2 * p],     AH, BH[p][0], BH[p][1]);
                MMA_AB(acc[mf][2 * p],     AH, BL[p][0], BL[p][1]);
                MMA_AB(acc[mf][2 * p],     AL, BH[p][0], BH[p][1]);
                MMA_AB(acc[mf][2 * p + 1], AH, BH[p][2], BH[p][3]);
                MMA_AB(acc[mf][2 * p + 1], AH, BL[p][2], BL[p][3]);
                MMA_AB(acc[mf][2 * p + 1], AL, BH[p][2], BH[p][3]);
            }
        }
    }
}

// ---------------- distance tile kernel: store D + fused sampled coarse hist ----------------
__global__ void __launch_bounds__(256) k_mma_dist(
    const __nv_bfloat16* __restrict__ Ahi, const __nv_bfloat16* __restrict__ Alo,
    const __nv_bfloat16* __restrict__ Bhi, const __nv_bfloat16* __restrict__ Blo,
    const float* __restrict__ x2v, const float* __restrict__ y2v,
    const float* __restrict__ wxv, const float* __restrict__ wyv,
    float* __restrict__ Dout, float* __restrict__ hist)
{
    extern __shared__ __align__(128) char smem[];
    int tid = threadIdx.x;
    int row0 = blockIdx.y * TB, col0 = blockIdx.x * TB;

    float* shh = (float*)(smem + OF_HIST);
    for (int i = tid; i < NB1; i += 256) shh[i] = 0.f;

    stage_tiles(smem, OF_TILES, tid, Ahi, Alo, row0, Bhi, Blo, col0);
    if (tid < TB) {
        ((float*)(smem + OF_X2))[tid] = x2v[row0 + tid];
        ((float*)(smem + OF_Y2))[tid] = y2v[col0 + tid];
        ((float*)(smem + OF_WX))[tid] = wxv[row0 + tid];
        ((float*)(smem + OF_WY))[tid] = wyv[col0 + tid];
    }
    __syncthreads();

    uint32_t sT = (uint32_t)__cvta_generic_to_shared(smem) + OF_TILES;
    float acc[4][4][4];
    mma_mainloop(sT, tid, acc);

    const int lane = tid & 31, warp = tid >> 5;
    const int wr = warp >> 2, wc = warp & 3;
    const int g = lane >> 2, t = lane & 3;
    const float* x2s = (const float*)(smem + OF_X2);
    const float* y2s = (const float*)(smem + OF_Y2);
    const float* wxs = (const float*)(smem + OF_WX);
    const float* wys = (const float*)(smem + OF_WY);
    bool samp = (g == 0) && ((t & 1) == 0);

    #pragma unroll
    for (int mf = 0; mf < 4; mf++) {
        int r0 = wr * 64 + mf * 16 + g;
        float x0 = x2s[r0], x1 = x2s[r0 + 8];
        #pragma unroll
        for (int nf = 0; nf < 4; nf++) {
            int c0 = wc * 32 + nf * 8 + 2 * t;
            float y0 = y2s[c0], y1 = y2s[c0 + 1];
            float2 o0, o1;
            o0.x = fmaxf(x0 + y0 - 2.f * acc[mf][nf][0], 0.f) * (1.f / DF);
            o0.y = fmaxf(x0 + y1 - 2.f * acc[mf][nf][1], 0.f) * (1.f / DF);
            o1.x = fmaxf(x1 + y0 - 2.f * acc[mf][nf][2], 0.f) * (1.f / DF);
            o1.y = fmaxf(x1 + y1 - 2.f * acc[mf][nf][3], 0.f) * (1.f / DF);
            *(float2*)&Dout[(size_t)(row0 + r0) * NPTS + col0 + c0] = o0;
            *(float2*)&Dout[(size_t)(row0 + r0 + 8) * NPTS + col0 + c0] = o1;
            if (samp) {
                float wy0 = wys[c0];
                int b0 = min((int)(o0.x * SC1), NB1 - 1);
                int b1 = min((int)(o1.x * SC1), NB1 - 1);
                atomicAdd(&shh[b0], wxs[r0] * wy0);
                atomicAdd(&shh[b1], wxs[r0 + 8] * wy0);
            }
        }
    }
    __syncthreads();
    for (int i = tid; i < NB1; i += 256) {
        float v = shh[i];
        if (v != 0.f) atomicAdd(&hist[i], v);
    }
}

// ---------------- final fused: recompute tiles, K-weighted row sums (z=0 ae, z=1 aa) ----------------
__global__ void __launch_bounds__(256) k_final(
    const __nv_bfloat16* __restrict__ hiA, const __nv_bfloat16* __restrict__ loA,
    const __nv_bfloat16* __restrict__ hiB, const __nv_bfloat16* __restrict__ loB,
    const float* __restrict__ x2v, const float* __restrict__ y2v,
    const float* __restrict__ w, const float* __restrict__ ew)
{
    extern __shared__ __align__(128) char smem[];
    int tid = threadIdx.x;
    int row0 = blockIdx.y * TB, col0 = blockIdx.x * TB;
    bool ae = (blockIdx.z == 0);

    const __nv_bfloat16* Bh = ae ? hiB : hiA;
    const __nv_bfloat16* Bl = ae ? loB : loA;
    const float* y2p = ae ? y2v : x2v;
    const float* wyp = ae ? ew : w;

    stage_tiles(smem, FOF_TILES, tid, hiA, loA, row0, Bh, Bl, col0);
    if (tid < TB) {
        ((float*)(smem + FOF_X2))[tid] = x2v[row0 + tid];
        ((float*)(smem + FOF_Y2))[tid] = y2p[col0 + tid];
        ((float*)(smem + FOF_W))[tid]  = wyp[col0 + tid];
        ((float*)(smem + FOF_RS))[tid] = 0.f;
    }
    __syncthreads();

    uint32_t sT = (uint32_t)__cvta_generic_to_shared(smem) + FOF_TILES;
    float acc[4][4][4];
    mma_mainloop(sT, tid, acc);

    const int lane = tid & 31, warp = tid >> 5;
    const int wr = warp >> 2, wc = warp & 3;
    const int g = lane >> 2, t = lane & 3;
    const float* x2s = (const float*)(smem + FOF_X2);
    const float* y2s = (const float*)(smem + FOF_Y2);
    const float* ws  = (const float*)(smem + FOF_W);
    float* rowsum = (float*)(smem + FOF_RS);

    float G1 = (float)g_scal[6], G2 = (float)g_scal[7];

    #pragma unroll
    for (int mf = 0; mf < 4; mf++) {
        int r0 = wr * 64 + mf * 16 + g;
        float x0 = x2s[r0], x1 = x2s[r0 + 8];
        float p0 = 0.f, p1 = 0.f;
        #pragma unroll
        for (int nf = 0; nf < 4; nf++) {
            int c0 = wc * 32 + nf * 8 + 2 * t;
            float y0 = y2s[c0], y1 = y2s[c0 + 1];
            float w0 = ws[c0],  w1 = ws[c0 + 1];
            float d00 = fmaxf(x0 + y0 - 2.f * acc[mf][nf][0], 0.f) * (1.f / DF);
            float d01 = fmaxf(x0 + y1 - 2.f * acc[mf][nf][1], 0.f) * (1.f / DF);
            float d10 = fmaxf(x1 + y0 - 2.f * acc[mf][nf][2], 0.f) * (1.f / DF);
            float d11 = fmaxf(x1 + y1 - 2.f * acc[mf][nf][3], 0.f) * (1.f / DF);
            p0 += (__expf(-G1 * d00) + __expf(-G2 * d00)) * w0
                + (__expf(-G1 * d01) + __expf(-G2 * d01)) * w1;
            p1 += (__expf(-G1 * d10) + __expf(-G2 * d10)) * w0
                + (__expf(-G1 * d11) + __expf(-G2 * d11)) * w1;
        }
        atomicAdd(&rowsum[r0], p0);
        atomicAdd(&rowsum[r0 + 8], p1);
    }
    __syncthreads();
    if (tid < TB) {
        float* Sout = ae ? g_Sae : g_Saa;
        atomicAdd(&Sout[row0 + tid], rowsum[tid]);
    }
}

// ---------------- scan coarse hist -> window (±16 bins) ----------------
__global__ void k_scan0() {
    int which = blockIdx.x;
    const float* h = g_hcoarse + which * NB1;
    __shared__ double part[256];
    int tid = threadIdx.x;
    double loc[8], s = 0.0;
    #pragma unroll
    for (int i = 0; i < 8; i++) { loc[i] = h[tid * 8 + i]; s += loc[i]; }
    part[tid] = s; __syncthreads();
    for (int off = 1; off < 256; off <<= 1) {
        double v = (tid >= off) ? part[tid - off] : 0.0;
        __syncthreads();
        part[tid] += v;
        __syncthreads();
    }
    double T = 0.5 * part[255];
    double c = tid ? part[tid - 1] : 0.0;
    int b = -1;
    #pragma unroll
    for (int i = 0; i < 8; i++) {
        double nc = c + loc[i];
        if (b < 0 && c < T && nc >= T) b = tid * 8 + i;
        c = nc;
    }
    if (b >= 0) {
        int blo = b > 16 ? b - 16 : 0;
        int bhi = b + 17 > NB1 ? NB1 : b + 17;
        g_scal[2 + 2 * which] = blo * (16.0 / NB1);
        g_scal[3 + 2 * which] = (bhi - blo) * (16.0 / NB1);
    }
}

// ---------------- combined refine pass: blocks <1024 ae, >=1024 ee ----------------
__global__ void k_refine(const float* __restrict__ Dae, const float* __restrict__ Dee,
                         const float* __restrict__ w, const float* __restrict__ ew,
                         float* __restrict__ histA, double* __restrict__ below)
{
    __shared__ float shh[NBF];
    __shared__ double red[256];
    int tid = threadIdx.x;
    int which = blockIdx.x >> 10;            // 0 ae, 1 ee
    int blk   = blockIdx.x & 1023;
    const float* D  = which ? Dee : Dae;
    const float* wx = which ? ew : w;
    const float* wy = ew;
    float lo    = (float)g_scal[2 + 2 * which];
    float scale = (float)((double)NBF / g_scal[3 + 2 * which]);
    float* hist = histA + which * NBF;

    for (int i = tid; i < NBF; i += 256) shh[i] = 0.f;
    __syncthreads();
    const float4* D4  = (const float4*)D;
    const float4* WY4 = (const float4*)wy;
    size_t base = (size_t)blk * 4096;
    float bacc = 0.f;
    #pragma unroll 2
    for (int s = 0; s < 16; s++) {
        size_t idx = base + (size_t)s * 256 + tid;
        float4 v = D4[idx];
        int i  = (int)(idx >> 10);
        int j4 = (int)(idx & 1023);
        float wi = wx[i];
        float4 wv4 = WY4[j4];
        float vv[4] = {v.x, v.y, v.z, v.w};
        float ww[4] = {wv4.x, wv4.y, wv4.z, wv4.w};
        #pragma unroll
        for (int u = 0; u < 4; u++) {
            if (vv[u] < lo) bacc += wi * ww[u];
            else {
                int b = (int)((vv[u] - lo) * scale);
                if (b < NBF) atomicAdd(&shh[b], wi * ww[u]);
            }
        }
    }
    red[tid] = bacc; __syncthreads();
    for (int off = 128; off; off >>= 1) {
        if (tid < off) red[tid] += red[tid + off];
        __syncthreads();
    }
    if (tid == 0) atomicAdd(&below[which], red[0]);
    for (int i = tid; i < NBF; i += 256) {
        float v = shh[i];
        if (v != 0.f) atomicAdd(&hist[i], v);
    }
}

// ---------------- scan fine hist -> g ----------------
__global__ void k_scanF() {
    int which = blockIdx.x;
    const float* h = g_hfine + which * NBF;
    __shared__ double part[1024];
    int tid = threadIdx.x;
    double loc[8], s = 0.0;
    #pragma unroll
    for (int i = 0; i < 8; i++) { loc[i] = h[tid * 8 + i]; s += loc[i]; }
    part[tid] = s; __syncthreads();
    for (int off = 1; off < 1024; off <<= 1) {
        double v = (tid >= off) ? part[tid - off] : 0.0;
        __syncthreads();
        part[tid] += v;
        __syncthreads();
    }
    double Wtot = (which == 0) ? g_scal[0] * g_scal[1] : g_scal[1] * g_scal[1];
    double T = 0.5 * Wtot - g_below[which];
    double lo = g_scal[2 + 2 * which], wdt = g_scal[3 + 2 * which];
    double c = tid ? part[tid - 1] : 0.0;
    int b = -1;
    #pragma unroll
    for (int i = 0; i < 8; i++) {
        double nc = c + loc[i];
        if (b < 0 && c < T && nc >= T) b = tid * 8 + i;
        c = nc;
    }
    if (tid == 0 && T <= 0.0) b = 0;
    if (tid == 1023 && T > 0.0 && part[1023] < T && b < 0) b = NBF - 1;
    if (b >= 0) {
        double tt = lo + (b + 0.5) * (wdt / NBF);
        g_scal[6 + which] = 1.0 / (tt + 1e-8);
    }
}

// ---------------- final combine ----------------
__global__ void k_combine(const float* __restrict__ w, float* __restrict__ out) {
    int i = blockIdx.x * blockDim.x + threadIdx.x;
    if (i < NPTS) {
        float Ws  = (float)g_scal[0];
        float EWs = (float)g_scal[1];
        out[i] = (w[i] / Ws) * (g_Sae[i] / EWs - g_Saa[i] / Ws);
    }
}

// ---------------- host launcher ----------------
extern "C" void kernel_launch(void* const* d_in, const int* in_sizes, int n_in,
                              void* d_out, int out_size)
{
    const float* state   = (const float*)d_in[0];
    const float* action  = (const float*)d_in[1];
    const float* estate  = (const float*)d_in[2];
    const float* eaction = (const float*)d_in[3];
    const float* w       = (const float*)d_in[4];
    const float* ew      = (const float*)d_in[5];
    float* out = (float*)d_out;

    cudaFuncSetAttribute(k_mma_dist, cudaFuncAttributeMaxDynamicSharedMemorySize, SMEM_DIST);
    cudaFuncSetAttribute(k_final,    cudaFuncAttributeMaxDynamicSharedMemorySize, SMEM_FIN);

    float *p_hc, *p_hf, *p_Dae, *p_Dee, *p_x2, *p_y2;
    __nv_bfloat16 *p_hiA, *p_loA, *p_hiB, *p_loB;
    double* p_below;
    cudaGetSymbolAddress((void**)&p_hc,    g_hcoarse);
    cudaGetSymbolAddress((void**)&p_hf,    g_hfine);
    cudaGetSymbolAddress((void**)&p_Dae,   g_Dae);
    cudaGetSymbolAddress((void**)&p_Dee,   g_Dee);
    cudaGetSymbolAddress((void**)&p_x2,    g_x2);
    cudaGetSymbolAddress((void**)&p_y2,    g_y2);
    cudaGetSymbolAddress((void**)&p_hiA,   g_hiA);
    cudaGetSymbolAddress((void**)&p_loA,   g_loA);
    cudaGetSymbolAddress((void**)&p_hiB,   g_hiB);
    cudaGetSymbolAddress((void**)&p_loB,   g_loB);
    cudaGetSymbolAddress((void**)&p_below, g_below);

    dim3 g32(NTILE, NTILE);
    dim3 gfin(NTILE, NTILE, 2);

    k_zero<<<128, 256>>>();
    k_cvt<<<2048, 256>>>(state, action, estate, eaction);
    k_wsum<<<1, 1024>>>(w, ew);

    k_mma_dist<<<g32, 256, SMEM_DIST>>>(p_hiA, p_loA, p_hiB, p_loB,
                                        p_x2, p_y2, w, ew, p_Dae, p_hc);
    k_mma_dist<<<g32, 256, SMEM_DIST>>>(p_hiB, p_loB, p_hiB, p_loB,
                                        p_y2, p_y2, ew, ew, p_Dee, p_hc + NB1);

    k_scan0<<<2, 256>>>();

    k_refine<<<2048, 256>>>(p_Dae, p_Dee, w, ew, p_hf, p_below);

    k_scanF<<<2, 1024>>>();

    k_final<<<gfin, 256, SMEM_FIN>>>(p_hiA, p_loA, p_hiB, p_loB, p_x2, p_y2, w, ew);

    k_combine<<<16, 256>>>(w, out);
}

// round 9
// speedup vs baseline: 2.6084x; 1.0130x over previous
#include <cuda_runtime.h>
#include <cuda_bf16.h>
#include <math.h>
#include <stdint.h>

#define NPTS 4096
#define DS 48
#define DA 16
#define DF 64
#define TB 128
#define NTILE (NPTS / TB)      /* 32 */
#define NB1 2048               /* coarse bins over [0,16] */
#define SC1 128.0f             /* NB1/16 */
#define NBF 8192               /* fine bins in refine pass */

// ---------------- device scratch (no big D matrices anymore) ----------------
__device__ __nv_bfloat16 g_hiA[(size_t)NPTS * DF], g_loA[(size_t)NPTS * DF];
__device__ __nv_bfloat16 g_hiB[(size_t)NPTS * DF], g_loB[(size_t)NPTS * DF];
__device__ float  g_x2[NPTS];
__device__ float  g_y2[NPTS];
__device__ float  g_hcoarse[2 * NB1];
__device__ float  g_hfine[2 * NBF];
__device__ double g_below[2];
__device__ double g_scal[8];   // 0 Wsum,1 EWsum,2/3 lo/width ae,4/5 lo/width ee,6 g1,7 g2
__device__ float  g_Sae[NPTS];
__device__ float  g_Saa[NPTS];

// ---------------- mma / ldmatrix helpers ----------------
#define MMA_AB(d, A, b0, b1)                                                \
    asm volatile(                                                           \
        "mma.sync.aligned.m16n8k16.row.col.f32.bf16.bf16.f32 "              \
        "{%0,%1,%2,%3}, {%4,%5,%6,%7}, {%8,%9}, {%0,%1,%2,%3};"             \
        : "+f"((d)[0]), "+f"((d)[1]), "+f"((d)[2]), "+f"((d)[3])            \
        : "r"((A)[0]), "r"((A)[1]), "r"((A)[2]), "r"((A)[3]), "r"(b0), "r"(b1))

__device__ __forceinline__ void ldsm4(uint32_t a, uint32_t d[4]) {
    asm volatile("ldmatrix.sync.aligned.m8n8.x4.shared.b16 {%0,%1,%2,%3}, [%4];"
                 : "=r"(d[0]), "=r"(d[1]), "=r"(d[2]), "=r"(d[3]) : "r"(a));
}

// swizzled offset within a 128x(64 bf16) tile: 128-byte rows, XOR on 16B units
#define SWO(r, kc) ((uint32_t)(r) * 128u + (((uint32_t)(kc)) ^ (((uint32_t)(r) & 7u) << 4)))

#define TILE_BYTES 16384

// ---------------- staging: global (row-major 128B rows) -> swizzled smem tile ----------------
__device__ __forceinline__ void stage_one(char* dst, const __nv_bfloat16* src,
                                          int row0, int rstride, int tid) {
    const uint4* p = (const uint4*)src;
    #pragma unroll
    for (int idx = tid; idx < 1024; idx += 256) {
        int r = idx >> 3, c = idx & 7;
        uint32_t off = (uint32_t)r * 128u + (((uint32_t)c * 16u) ^ (((uint32_t)r & 7u) << 4));
        *(uint4*)(dst + off) = p[(size_t)(row0 + r * rstride) * 8 + c];
    }
}

// ---------------- mainloop: ldmatrix.x4 + bf16 mma (1 or 3 products) ----------------
template <bool THREE>
__device__ __forceinline__ void mma_loop(uint32_t sAh, uint32_t sAl,
                                         uint32_t sBh, uint32_t sBl,
                                         int tid, float acc[4][4][4]) {
    const int lane = tid & 31, warp = tid >> 5;
    const int wr = warp >> 2, wc = warp & 3;

    #pragma unroll
    for (int mf = 0; mf < 4; mf++)
        #pragma unroll
        for (int nf = 0; nf < 4; nf++)
            #pragma unroll
            for (int u = 0; u < 4; u++) acc[mf][nf][u] = 0.f;

    const int aRow = lane & 15;
    const int aKc  = (lane >> 4) << 4;
    const int bRow = ((lane & 16) >> 1) + (lane & 7);
    const int bKc  = (lane & 8) ? 16 : 0;

    #pragma unroll
    for (int ks = 0; ks < 4; ks++) {
        const int kc0 = ks * 32;
        uint32_t BH[2][4], BL[2][4];
        #pragma unroll
        for (int p = 0; p < 2; p++) {
            uint32_t off = SWO(wc * 32 + p * 16 + bRow, kc0 + bKc);
            ldsm4(sBh + off, BH[p]);
            if (THREE) ldsm4(sBl + off, BL[p]);
        }
        #pragma unroll
        for (int mf = 0; mf < 4; mf++) {
            uint32_t off = SWO(wr * 64 + mf * 16 + aRow, kc0 + aKc);
            uint32_t AH[4], AL[4];
            ldsm4(sAh + off, AH);
            if (THREE) ldsm4(sAl + off, AL);
            #pragma unroll
            for (int p = 0; p < 2; p++) {
                MMA_AB(acc[mf][2 * p],     AH, BH[p][0], BH[p][1]);
                MMA_AB(acc[mf][2 * p + 1], AH, BH[p][2], BH[p][3]);
                if (THREE) {
                    MMA_AB(acc[mf][2 * p],     AH, BL[p][0], BL[p][1]);
                    MMA_AB(acc[mf][2 * p],     AL, BH[p][0], BH[p][1]);
                    MMA_AB(acc[mf][2 * p + 1], AH, BL[p][2], BL[p][3]);
                    MMA_AB(acc[mf][2 * p + 1], AL, BH[p][2], BH[p][3]);
                }
            }
        }
    }
}

// ---------------- zero per-replay accumulators ----------------
__global__ void k_zero() {
    int i = blockIdx.x * blockDim.x + threadIdx.x;
    if (i < 2 * NB1) g_hcoarse[i] = 0.f;
    if (i < 2 * NBF) g_hfine[i]   = 0.f;
    if (i < NPTS)  { g_Saa[i] = 0.f; g_Sae[i] = 0.f; }
    if (i < 2)       g_below[i]   = 0.0;
}

// ---------------- convert inputs to bf16 hi/lo + row norms (coalesced) ----------------
__global__ void k_cvt(const float* __restrict__ ss, const float* __restrict__ aa_,
                      const float* __restrict__ es, const float* __restrict__ ea) {
    __shared__ float part[8];
    int tid = threadIdx.x;
    int gr = blockIdx.x * 4 + (tid >> 6);
    int k  = tid & 63;
    bool isA = (gr < NPTS);
    int r = isA ? gr : gr - NPTS;
    const float* sp = isA ? ss : es;
    const float* ap = isA ? aa_ : ea;
    __nv_bfloat16* hi = isA ? g_hiA : g_hiB;
    __nv_bfloat16* lo = isA ? g_loA : g_loB;

    float v = (k < DS) ? sp[(size_t)r * DS + k] : ap[(size_t)r * DA + (k - DS)];
    __nv_bfloat16 h = __float2bfloat16(v);
    hi[(size_t)r * DF + k] = h;
    lo[(size_t)r * DF + k] = __float2bfloat16(v - __bfloat162float(h));

    float sq = v * v;
    #pragma unroll
    for (int off = 16; off; off >>= 1) sq += __shfl_xor_sync(0xFFFFFFFF, sq, off);
    if ((tid & 31) == 0) part[tid >> 5] = sq;
    __syncthreads();
    if ((tid & 63) == 0) {
        float s = part[(tid >> 5)] + part[(tid >> 5) + 1];
        if (isA) g_x2[r] = s; else g_y2[r] = s;
    }
}

// ---------------- weight sums (double) ----------------
__global__ void k_wsum(const float* __restrict__ w, const float* __restrict__ ew) {
    __shared__ double sh[1024];
    int tid = threadIdx.x;
    double s1 = 0.0, s2 = 0.0;
    for (int i = tid; i < NPTS; i += 1024) { s1 += w[i]; s2 += ew[i]; }
    sh[tid] = s1; __syncthreads();
    for (int off = 512; off; off >>= 1) { if (tid < off) sh[tid] += sh[tid + off]; __syncthreads(); }
    if (tid == 0) g_scal[0] = sh[0];
    __syncthreads();
    sh[tid] = s2; __syncthreads();
    for (int off = 512; off; off >>= 1) { if (tid < off) sh[tid] += sh[tid + off]; __syncthreads(); }
    if (tid == 0) g_scal[1] = sh[0];
}

// ---------------- sampled coarse hist via hi-only MMA ----------------
// grid (32 coltiles, 2 rowgroups, 2 matrices); rows sampled stride 16
#define HOF_X2    0
#define HOF_Y2    512
#define HOF_WX    1024
#define HOF_WY    1536
#define HOF_HIST  2048
#define HOF_TILES 10240
#define SMEM_HS   (HOF_TILES + 2 * TILE_BYTES)   /* 43008 */

__global__ void __launch_bounds__(256) k_hist_sampled(
    const float* __restrict__ w, const float* __restrict__ ew)
{
    extern __shared__ __align__(128) char smem[];
    int tid = threadIdx.x;
    bool ae = (blockIdx.z == 0);
    int col0 = blockIdx.x * TB;
    int rbase = blockIdx.y * TB;             // sampled-row index base (row = idx*16)

    const __nv_bfloat16* Ah = ae ? g_hiA : g_hiB;
    const __nv_bfloat16* Bh = g_hiB;
    const float* x2p = ae ? g_x2 : g_y2;
    const float* wxp = ae ? w : ew;

    float* shh = (float*)(smem + HOF_HIST);
    for (int i = tid; i < NB1; i += 256) shh[i] = 0.f;

    stage_one(smem + HOF_TILES,              Ah, rbase * 16, 16, tid);
    stage_one(smem + HOF_TILES + TILE_BYTES, Bh, col0,        1, tid);
    if (tid < TB) {
        ((float*)(smem + HOF_X2))[tid] = x2p[(rbase + tid) * 16];
        ((float*)(smem + HOF_WX))[tid] = wxp[(rbase + tid) * 16];
        ((float*)(smem + HOF_Y2))[tid] = g_y2[col0 + tid];
        ((float*)(smem + HOF_WY))[tid] = ew[col0 + tid];
    }
    __syncthreads();

    uint32_t sT = (uint32_t)__cvta_generic_to_shared(smem) + HOF_TILES;
    float acc[4][4][4];
    mma_loop<false>(sT, 0, sT + TILE_BYTES, 0, tid, acc);

    const int lane = tid & 31, warp = tid >> 5;
    const int wr = warp >> 2, wc = warp & 3;
    const int g = lane >> 2, t = lane & 3;
    const float* x2s = (const float*)(smem + HOF_X2);
    const float* y2s = (const float*)(smem + HOF_Y2);
    const float* wxs = (const float*)(smem + HOF_WX);
    const float* wys = (const float*)(smem + HOF_WY);

    #pragma unroll
    for (int mf = 0; mf < 4; mf++) {
        int r0 = wr * 64 + mf * 16 + g;
        float x0 = x2s[r0], x1 = x2s[r0 + 8];
        float wx0 = wxs[r0], wx1 = wxs[r0 + 8];
        #pragma unroll
        for (int nf = 0; nf < 4; nf++) {
            int c0 = wc * 32 + nf * 8 + 2 * t;
            float y0 = y2s[c0], y1 = y2s[c0 + 1];
            float wy0 = wys[c0], wy1 = wys[c0 + 1];
            float d00 = fmaxf(x0 + y0 - 2.f * acc[mf][nf][0], 0.f) * (1.f / DF);
            float d01 = fmaxf(x0 + y1 - 2.f * acc[mf][nf][1], 0.f) * (1.f / DF);
            float d10 = fmaxf(x1 + y0 - 2.f * acc[mf][nf][2], 0.f) * (1.f / DF);
            float d11 = fmaxf(x1 + y1 - 2.f * acc[mf][nf][3], 0.f) * (1.f / DF);
            atomicAdd(&shh[min((int)(d00 * SC1), NB1 - 1)], wx0 * wy0);
            atomicAdd(&shh[min((int)(d01 * SC1), NB1 - 1)], wx0 * wy1);
            atomicAdd(&shh[min((int)(d10 * SC1), NB1 - 1)], wx1 * wy0);
            atomicAdd(&shh[min((int)(d11 * SC1), NB1 - 1)], wx1 * wy1);
        }
    }
    __syncthreads();
    float* hist = g_hcoarse + (ae ? 0 : NB1);
    for (int i = tid; i < NB1; i += 256) {
        float v = shh[i];
        if (v != 0.f) atomicAdd(&hist[i], v);
    }
}

// ---------------- scan coarse hist -> window (±16 bins) ----------------
__global__ void k_scan0() {
    int which = blockIdx.x;
    const float* h = g_hcoarse + which * NB1;
    __shared__ double part[256];
    int tid = threadIdx.x;
    double loc[8], s = 0.0;
    #pragma unroll
    for (int i = 0; i < 8; i++) { loc[i] = h[tid * 8 + i]; s += loc[i]; }
    part[tid] = s; __syncthreads();
    for (int off = 1; off < 256; off <<= 1) {
        double v = (tid >= off) ? part[tid - off] : 0.0;
        __syncthreads();
        part[tid] += v;
        __syncthreads();
    }
    double T = 0.5 * part[255];
    double c = tid ? part[tid - 1] : 0.0;
    int b = -1;
    #pragma unroll
    for (int i = 0; i < 8; i++) {
        double nc = c + loc[i];
        if (b < 0 && c < T && nc >= T) b = tid * 8 + i;
        c = nc;
    }
    if (b >= 0) {
        int blo = b > 16 ? b - 16 : 0;
        int bhi = b + 17 > NB1 ? NB1 : b + 17;
        g_scal[2 + 2 * which] = blo * (16.0 / NB1);
        g_scal[3 + 2 * which] = (bhi - blo) * (16.0 / NB1);
    }
}

// ---------------- refine via MMA recompute: below-mass + fine hist in window ----------------
#define ROF_X2    0
#define ROF_Y2    512
#define ROF_WX    1024
#define ROF_WY    1536
#define ROF_HIST  2048                      /* NBF*4 = 32768 */
#define ROF_TILES 34816
#define SMEM_RF   (ROF_TILES + 4 * TILE_BYTES)   /* 100352 */

__global__ void __launch_bounds__(256) k_refine_mma(
    const float* __restrict__ w, const float* __restrict__ ew)
{
    extern __shared__ __align__(128) char smem[];
    int tid = threadIdx.x;
    bool ae = (blockIdx.z == 0);
    int row0 = blockIdx.y * TB, col0 = blockIdx.x * TB;

    const __nv_bfloat16* Ah = ae ? g_hiA : g_hiB;
    const __nv_bfloat16* Al = ae ? g_loA : g_loB;
    const float* x2p = ae ? g_x2 : g_y2;
    const float* wxp = ae ? w : ew;
    int which = ae ? 0 : 1;

    float* shh = (float*)(smem + ROF_HIST);
    for (int i = tid; i < NBF; i += 256) shh[i] = 0.f;

    stage_one(smem + ROF_TILES,                  Ah,    row0, 1, tid);
    stage_one(smem + ROF_TILES + TILE_BYTES,     Al,    row0, 1, tid);
    stage_one(smem + ROF_TILES + 2 * TILE_BYTES, g_hiB, col0, 1, tid);
    stage_one(smem + ROF_TILES + 3 * TILE_BYTES, g_loB, col0, 1, tid);
    if (tid < TB) {
        ((float*)(smem + ROF_X2))[tid] = x2p[row0 + tid];
        ((float*)(smem + ROF_WX))[tid] = wxp[row0 + tid];
        ((float*)(smem + ROF_Y2))[tid] = g_y2[col0 + tid];
        ((float*)(smem + ROF_WY))[tid] = ew[col0 + tid];
    }
    __syncthreads();

    uint32_t sT = (uint32_t)__cvta_generic_to_shared(smem) + ROF_TILES;
    float acc[4][4][4];
    mma_loop<true>(sT, sT + TILE_BYTES, sT + 2 * TILE_BYTES, sT + 3 * TILE_BYTES, tid, acc);

    const int lane = tid & 31, warp = tid >> 5;
    const int wr = warp >> 2, wc = warp & 3;
    const int g = lane >> 2, t = lane & 3;
    const float* x2s = (const float*)(smem + ROF_X2);
    const float* y2s = (const float*)(smem + ROF_Y2);
    const float* wxs = (const float*)(smem + ROF_WX);
    const float* wys = (const float*)(smem + ROF_WY);

    float lo    = (float)g_scal[2 + 2 * which];
    float scale = (float)((double)NBF / g_scal[3 + 2 * which]);
    float bacc = 0.f;

    #pragma unroll
    for (int mf = 0; mf < 4; mf++) {
        int r0 = wr * 64 + mf * 16 + g;
        float x0 = x2s[r0], x1 = x2s[r0 + 8];
        float wx0 = wxs[r0], wx1 = wxs[r0 + 8];
        #pragma unroll
        for (int nf = 0; nf < 4; nf++) {
            int c0 = wc * 32 + nf * 8 + 2 * t;
            float y0 = y2s[c0], y1 = y2s[c0 + 1];
            float wy0 = wys[c0], wy1 = wys[c0 + 1];
            float dd[4], wt[4];
            dd[0] = fmaxf(x0 + y0 - 2.f * acc[mf][nf][0], 0.f) * (1.f / DF); wt[0] = wx0 * wy0;
            dd[1] = fmaxf(x0 + y1 - 2.f * acc[mf][nf][1], 0.f) * (1.f / DF); wt[1] = wx0 * wy1;
            dd[2] = fmaxf(x1 + y0 - 2.f * acc[mf][nf][2], 0.f) * (1.f / DF); wt[2] = wx1 * wy0;
            dd[3] = fmaxf(x1 + y1 - 2.f * acc[mf][nf][3], 0.f) * (1.f / DF); wt[3] = wx1 * wy1;
            #pragma unroll
            for (int u = 0; u < 4; u++) {
                if (dd[u] < lo) bacc += wt[u];
                else {
                    int b = (int)((dd[u] - lo) * scale);
                    if (b < NBF) atomicAdd(&shh[b], wt[u]);
                }
            }
        }
    }
    // reduce below-mass
    __shared__ float red[256];
    red[tid] = bacc; __syncthreads();
    for (int off = 128; off; off >>= 1) {
        if (tid < off) red[tid] += red[tid + off];
        __syncthreads();
    }
    if (tid == 0) atomicAdd(&g_below[which], (double)red[0]);
    float* hist = g_hfine + which * NBF;
    for (int i = tid; i < NBF; i += 256) {
        float v = shh[i];
        if (v != 0.f) atomicAdd(&hist[i], v);
    }
}

// ---------------- scan fine hist -> g ----------------
__global__ void k_scanF() {
    int which = blockIdx.x;
    const float* h = g_hfine + which * NBF;
    __shared__ double part[1024];
    int tid = threadIdx.x;
    double loc[8], s = 0.0;
    #pragma unroll
    for (int i = 0; i < 8; i++) { loc[i] = h[tid * 8 + i]; s += loc[i]; }
    part[tid] = s; __syncthreads();
    for (int off = 1; off < 1024; off <<= 1) {
        double v = (tid >= off) ? part[tid - off] : 0.0;
        __syncthreads();
        part[tid] += v;
        __syncthreads();
    }
    double Wtot = (which == 0) ? g_scal[0] * g_scal[1] : g_scal[1] * g_scal[1];
    double T = 0.5 * Wtot - g_below[which];
    double lo = g_scal[2 + 2 * which], wdt = g_scal[3 + 2 * which];
    double c = tid ? part[tid - 1] : 0.0;
    int b = -1;
    #pragma unroll
    for (int i = 0; i < 8; i++) {
        double nc = c + loc[i];
        if (b < 0 && c < T && nc >= T) b = tid * 8 + i;
        c = nc;
    }
    if (tid == 0 && T <= 0.0) b = 0;
    if (tid == 1023 && T > 0.0 && part[1023] < T && b < 0) b = NBF - 1;
    if (b >= 0) {
        double tt = lo + (b + 0.5) * (wdt / NBF);
        g_scal[6 + which] = 1.0 / (tt + 1e-8);
    }
}

// ---------------- final fused: recompute tiles, K-weighted row sums (z=0 ae, z=1 aa) ----------------
#define FOF_X2    0
#define FOF_Y2    512
#define FOF_W     1024
#define FOF_RS    1536
#define FOF_TILES 2048
#define SMEM_FIN  (FOF_TILES + 4 * TILE_BYTES)   /* 67584 */

__global__ void __launch_bounds__(256) k_final(
    const float* __restrict__ w, const float* __restrict__ ew)
{
    extern __shared__ __align__(128) char smem[];
    int tid = threadIdx.x;
    int row0 = blockIdx.y * TB, col0 = blockIdx.x * TB;
    bool ae = (blockIdx.z == 0);

    const __nv_bfloat16* Bh = ae ? g_hiB : g_hiA;
    const __nv_bfloat16* Bl = ae ? g_loB : g_loA;
    const float* y2p = ae ? g_y2 : g_x2;
    const float* wyp = ae ? ew : w;

    stage_one(smem + FOF_TILES,                  g_hiA, row0, 1, tid);
    stage_one(smem + FOF_TILES + TILE_BYTES,     g_loA, row0, 1, tid);
    stage_one(smem + FOF_TILES + 2 * TILE_BYTES, Bh,    col0, 1, tid);
    stage_one(smem + FOF_TILES + 3 * TILE_BYTES, Bl,    col0, 1, tid);
    if (tid < TB) {
        ((float*)(smem + FOF_X2))[tid] = g_x2[row0 + tid];
        ((float*)(smem + FOF_Y2))[tid] = y2p[col0 + tid];
        ((float*)(smem + FOF_W))[tid]  = wyp[col0 + tid];
        ((float*)(smem + FOF_RS))[tid] = 0.f;
    }
    __syncthreads();

    uint32_t sT = (uint32_t)__cvta_generic_to_shared(smem) + FOF_TILES;
    float acc[4][4][4];
    mma_loop<true>(sT, sT + TILE_BYTES, sT + 2 * TILE_BYTES, sT + 3 * TILE_BYTES, tid, acc);

    const int lane = tid & 31, warp = tid >> 5;
    const int wr = warp >> 2, wc = warp & 3;
    const int g = lane >> 2, t = lane & 3;
    const float* x2s = (const float*)(smem + FOF_X2);
    const float* y2s = (const float*)(smem + FOF_Y2);
    const float* ws  = (const float*)(smem + FOF_W);
    float* rowsum = (float*)(smem + FOF_RS);

    float G1 = (float)g_scal[6], G2 = (float)g_scal[7];

    #pragma unroll
    for (int mf = 0; mf < 4; mf++) {
        int r0 = wr * 64 + mf * 16 + g;
        float x0 = x2s[r0], x1 = x2s[r0 + 8];
        float p0 = 0.f, p1 = 0.f;
        #pragma unroll
        for (int nf = 0; nf < 4; nf++) {
            int c0 = wc * 32 + nf * 8 + 2 * t;
            float y0 = y2s[c0], y1 = y2s[c0 + 1];
            float w0 = ws[c0],  w1 = ws[c0 + 1];
            float d00 = fmaxf(x0 + y0 - 2.f * acc[mf][nf][0], 0.f) * (1.f / DF);
            float d01 = fmaxf(x0 + y1 - 2.f * acc[mf][nf][1], 0.f) * (1.f / DF);
            float d10 = fmaxf(x1 + y0 - 2.f * acc[mf][nf][2], 0.f) * (1.f / DF);
            float d11 = fmaxf(x1 + y1 - 2.f * acc[mf][nf][3], 0.f) * (1.f / DF);
            p0 += (__expf(-G1 * d00) + __expf(-G2 * d00)) * w0
                + (__expf(-G1 * d01) + __expf(-G2 * d01)) * w1;
            p1 += (__expf(-G1 * d10) + __expf(-G2 * d10)) * w0
                + (__expf(-G1 * d11) + __expf(-G2 * d11)) * w1;
        }
        atomicAdd(&rowsum[r0], p0);
        atomicAdd(&rowsum[r0 + 8], p1);
    }
    __syncthreads();
    if (tid < TB) {
        float* Sout = ae ? g_Sae : g_Saa;
        atomicAdd(&Sout[row0 + tid], rowsum[tid]);
    }
}

// ---------------- final combine ----------------
__global__ void k_combine(const float* __restrict__ w, float* __restrict__ out) {
    int i = blockIdx.x * blockDim.x + threadIdx.x;
    if (i < NPTS) {
        float Ws  = (float)g_scal[0];
        float EWs = (float)g_scal[1];
        out[i] = (w[i] / Ws) * (g_Sae[i] / EWs - g_Saa[i] / Ws);
    }
}

// ---------------- host launcher ----------------
extern "C" void kernel_launch(void* const* d_in, const int* in_sizes, int n_in,
                              void* d_out, int out_size)
{
    const float* state   = (const float*)d_in[0];
    const float* action  = (const float*)d_in[1];
    const float* estate  = (const float*)d_in[2];
    const float* eaction = (const float*)d_in[3];
    const float* w       = (const float*)d_in[4];
    const float* ew      = (const float*)d_in[5];
    float* out = (float*)d_out;

    cudaFuncSetAttribute(k_hist_sampled, cudaFuncAttributeMaxDynamicSharedMemorySize, SMEM_HS);
    cudaFuncSetAttribute(k_refine_mma,   cudaFuncAttributeMaxDynamicSharedMemorySize, SMEM_RF);
    cudaFuncSetAttribute(k_final,        cudaFuncAttributeMaxDynamicSharedMemorySize, SMEM_FIN);

    dim3 ghs(NTILE, 2, 2);
    dim3 gfull(NTILE, NTILE, 2);

    k_zero<<<128, 256>>>();
    k_cvt<<<2048, 256>>>(state, action, estate, eaction);
    k_wsum<<<1, 1024>>>(w, ew);

    k_hist_sampled<<<ghs, 256, SMEM_HS>>>(w, ew);
    k_scan0<<<2, 256>>>();

    k_refine_mma<<<gfull, 256, SMEM_RF>>>(w, ew);
    k_scanF<<<2, 1024>>>();

    k_final<<<gfull, 256, SMEM_FIN>>>(w, ew);

    k_combine<<<16, 256>>>(w, out);
}

// round 10
// speedup vs baseline: 2.7252x; 1.0448x over previous
#include <cuda_runtime.h>
#include <cuda_bf16.h>
#include <math.h>
#include <stdint.h>

#define NPTS 4096
#define DS 48
#define DA 16
#define DF 64
#define TB 128
#define NTILE (NPTS / TB)      /* 32 */
#define NB1 2048               /* coarse bins over [0,16] */
#define SC1 128.0f             /* NB1/16 */
#define NBF 8192               /* fine bins in refine pass */

// ---------------- device scratch ----------------
__device__ __nv_bfloat16 g_hiA[(size_t)NPTS * DF], g_loA[(size_t)NPTS * DF];
__device__ __nv_bfloat16 g_hiB[(size_t)NPTS * DF], g_loB[(size_t)NPTS * DF];
__device__ float  g_x2[NPTS];
__device__ float  g_y2[NPTS];
__device__ float  g_hcoarse[2 * NB1];
__device__ float  g_hfine[2 * NBF];
__device__ double g_below[2];
__device__ double g_scal[8];   // 0 Wsum,1 EWsum,2/3 lo/width ae,4/5 lo/width ee,6 g1,7 g2
__device__ float  g_Sae[NPTS];
__device__ float  g_Saa[NPTS];

// ---------------- mma / ldmatrix helpers ----------------
#define MMA_AB(d, A, b0, b1)                                                \
    asm volatile(                                                           \
        "mma.sync.aligned.m16n8k16.row.col.f32.bf16.bf16.f32 "              \
        "{%0,%1,%2,%3}, {%4,%5,%6,%7}, {%8,%9}, {%0,%1,%2,%3};"             \
        : "+f"((d)[0]), "+f"((d)[1]), "+f"((d)[2]), "+f"((d)[3])            \
        : "r"((A)[0]), "r"((A)[1]), "r"((A)[2]), "r"((A)[3]), "r"(b0), "r"(b1))

__device__ __forceinline__ void ldsm4(uint32_t a, uint32_t d[4]) {
    asm volatile("ldmatrix.sync.aligned.m8n8.x4.shared.b16 {%0,%1,%2,%3}, [%4];"
                 : "=r"(d[0]), "=r"(d[1]), "=r"(d[2]), "=r"(d[3]) : "r"(a));
}

// swizzled offset within an Nx(64 bf16) tile: 128-byte rows, XOR on 16B units
#define SWO(r, kc) ((uint32_t)(r) * 128u + (((uint32_t)(kc)) ^ (((uint32_t)(r) & 7u) << 4)))

#define TILE_BYTES 16384   /* 128-row tile */

// ---------------- staging: global (row-major 128B rows) -> swizzled smem tile ----------------
__device__ __forceinline__ void stage_one(char* dst, const __nv_bfloat16* src,
                                          int row0, int rstride, int tid, int nrows) {
    const uint4* p = (const uint4*)src;
    for (int idx = tid; idx < nrows * 8; idx += 256) {
        int r = idx >> 3, c = idx & 7;
        uint32_t off = (uint32_t)r * 128u + (((uint32_t)c * 16u) ^ (((uint32_t)r & 7u) << 4));
        *(uint4*)(dst + off) = p[(size_t)(row0 + r * rstride) * 8 + c];
    }
}

// ---------------- mainloop: ldmatrix.x4 + bf16 mma; MF m-frags per warp, 1 or 3 products ----
template <int MF, bool THREE>
__device__ __forceinline__ void mma_loop(uint32_t sAh, uint32_t sAl,
                                         uint32_t sBh, uint32_t sBl,
                                         int tid, float acc[4][4][4]) {
    const int lane = tid & 31, warp = tid >> 5;
    const int wr = warp >> 2, wc = warp & 3;

    #pragma unroll
    for (int mf = 0; mf < MF; mf++)
        #pragma unroll
        for (int nf = 0; nf < 4; nf++)
            #pragma unroll
            for (int u = 0; u < 4; u++) acc[mf][nf][u] = 0.f;

    const int aRow = lane & 15;
    const int aKc  = (lane >> 4) << 4;
    const int bRow = ((lane & 16) >> 1) + (lane & 7);
    const int bKc  = (lane & 8) ? 16 : 0;

    #pragma unroll
    for (int ks = 0; ks < 4; ks++) {
        const int kc0 = ks * 32;
        uint32_t BH[2][4], BL[2][4];
        #pragma unroll
        for (int p = 0; p < 2; p++) {
            uint32_t off = SWO(wc * 32 + p * 16 + bRow, kc0 + bKc);
            ldsm4(sBh + off, BH[p]);
            if (THREE) ldsm4(sBl + off, BL[p]);
        }
        #pragma unroll
        for (int mf = 0; mf < MF; mf++) {
            uint32_t off = SWO(wr * (MF * 16) + mf * 16 + aRow, kc0 + aKc);
            uint32_t AH[4], AL[4];
            ldsm4(sAh + off, AH);
            if (THREE) ldsm4(sAl + off, AL);
            #pragma unroll
            for (int p = 0; p < 2; p++) {
                MMA_AB(acc[mf][2 * p],     AH, BH[p][0], BH[p][1]);
                MMA_AB(acc[mf][2 * p + 1], AH, BH[p][2], BH[p][3]);
                if (THREE) {
                    MMA_AB(acc[mf][2 * p],     AH, BL[p][0], BL[p][1]);
                    MMA_AB(acc[mf][2 * p],     AL, BH[p][0], BH[p][1]);
                    MMA_AB(acc[mf][2 * p + 1], AH, BL[p][2], BL[p][3]);
                    MMA_AB(acc[mf][2 * p + 1], AL, BH[p][2], BH[p][3]);
                }
            }
        }
    }
}

// ---------------- convert inputs to bf16 hi/lo + row norms + zero accumulators ----------------
__global__ void k_cvt(const float* __restrict__ ss, const float* __restrict__ aa_,
                      const float* __restrict__ es, const float* __restrict__ ea) {
    __shared__ float part[8];
    int tid = threadIdx.x;
    int gid = blockIdx.x * 256 + tid;
    if (gid < 2 * NB1) g_hcoarse[gid] = 0.f;
    if (gid < 2 * NBF) g_hfine[gid]   = 0.f;
    if (gid < NPTS)  { g_Saa[gid] = 0.f; g_Sae[gid] = 0.f; }
    if (gid < 2)       g_below[gid]   = 0.0;

    int gr = blockIdx.x * 4 + (tid >> 6);
    int k  = tid & 63;
    bool isA = (gr < NPTS);
    int r = isA ? gr : gr - NPTS;
    const float* sp = isA ? ss : es;
    const float* ap = isA ? aa_ : ea;
    __nv_bfloat16* hi = isA ? g_hiA : g_hiB;
    __nv_bfloat16* lo = isA ? g_loA : g_loB;

    float v = (k < DS) ? sp[(size_t)r * DS + k] : ap[(size_t)r * DA + (k - DS)];
    __nv_bfloat16 h = __float2bfloat16(v);
    hi[(size_t)r * DF + k] = h;
    lo[(size_t)r * DF + k] = __float2bfloat16(v - __bfloat162float(h));

    float sq = v * v;
    #pragma unroll
    for (int off = 16; off; off >>= 1) sq += __shfl_xor_sync(0xFFFFFFFF, sq, off);
    if ((tid & 31) == 0) part[tid >> 5] = sq;
    __syncthreads();
    if ((tid & 63) == 0) {
        float s = part[(tid >> 5)] + part[(tid >> 5) + 1];
        if (isA) g_x2[r] = s; else g_y2[r] = s;
    }
}

// ---------------- weight sums (double) ----------------
__global__ void k_wsum(const float* __restrict__ w, const float* __restrict__ ew) {
    __shared__ double sh[1024];
    int tid = threadIdx.x;
    double s1 = 0.0, s2 = 0.0;
    for (int i = tid; i < NPTS; i += 1024) { s1 += w[i]; s2 += ew[i]; }
    sh[tid] = s1; __syncthreads();
    for (int off = 512; off; off >>= 1) { if (tid < off) sh[tid] += sh[tid + off]; __syncthreads(); }
    if (tid == 0) g_scal[0] = sh[0];
    __syncthreads();
    sh[tid] = s2; __syncthreads();
    for (int off = 512; off; off >>= 1) { if (tid < off) sh[tid] += sh[tid + off]; __syncthreads(); }
    if (tid == 0) g_scal[1] = sh[0];
}

// ---------------- sampled coarse hist via hi-only MMA, M=64 tiles ----------------
// grid (32 coltiles, 4 rowgroups, 2 matrices); rows sampled stride 16
#define HOF_X2    0       /* 64 floats */
#define HOF_WX    256
#define HOF_Y2    512     /* 128 floats */
#define HOF_WY    1024
#define HOF_HIST  1536    /* 2 copies x NB1 = 16384 B */
#define HOF_TILES 17920   /* A 8192 + B 16384 */
#define SMEM_HS   (HOF_TILES + 8192 + 16384)   /* 42496 */

__global__ void __launch_bounds__(256) k_hist_sampled(
    const float* __restrict__ w, const float* __restrict__ ew)
{
    extern __shared__ __align__(128) char smem[];
    int tid = threadIdx.x;
    bool ae = (blockIdx.z == 0);
    int col0 = blockIdx.x * TB;
    int sbase = blockIdx.y * 64;             // sampled-row base; actual row = (sbase+r)*16

    const __nv_bfloat16* Ah = ae ? g_hiA : g_hiB;
    const float* x2p = ae ? g_x2 : g_y2;
    const float* wxp = ae ? w : ew;

    float* shh = (float*)(smem + HOF_HIST);
    for (int i = tid; i < 2 * NB1; i += 256) shh[i] = 0.f;

    stage_one(smem + HOF_TILES,        Ah,    sbase * 16, 16, tid, 64);
    stage_one(smem + HOF_TILES + 8192, g_hiB, col0,       1,  tid, 128);
    if (tid < 64) {
        ((float*)(smem + HOF_X2))[tid] = x2p[(sbase + tid) * 16];
        ((float*)(smem + HOF_WX))[tid] = wxp[(sbase + tid) * 16];
    }
    if (tid < TB) {
        ((float*)(smem + HOF_Y2))[tid] = g_y2[col0 + tid];
        ((float*)(smem + HOF_WY))[tid] = ew[col0 + tid];
    }
    __syncthreads();

    uint32_t sT = (uint32_t)__cvta_generic_to_shared(smem) + HOF_TILES;
    float acc[4][4][4];
    mma_loop<2, false>(sT, 0, sT + 8192, 0, tid, acc);

    const int lane = tid & 31, warp = tid >> 5;
    const int wr = warp >> 2, wc = warp & 3;
    const int g = lane >> 2, t = lane & 3;
    const float* x2s = (const float*)(smem + HOF_X2);
    const float* wxs = (const float*)(smem + HOF_WX);
    const float* y2s = (const float*)(smem + HOF_Y2);
    const float* wys = (const float*)(smem + HOF_WY);
    float* myh = shh + (warp & 1) * NB1;     // split copies to halve conflicts

    #pragma unroll
    for (int mf = 0; mf < 2; mf++) {
        int r0 = wr * 32 + mf * 16 + g;
        float x0 = x2s[r0], x1 = x2s[r0 + 8];
        float wx0 = wxs[r0], wx1 = wxs[r0 + 8];
        #pragma unroll
        for (int nf = 0; nf < 4; nf++) {
            int c0 = wc * 32 + nf * 8 + 2 * t;
            float y0 = y2s[c0], y1 = y2s[c0 + 1];
            float wy0 = wys[c0], wy1 = wys[c0 + 1];
            float d00 = fmaxf(x0 + y0 - 2.f * acc[mf][nf][0], 0.f) * (1.f / DF);
            float d01 = fmaxf(x0 + y1 - 2.f * acc[mf][nf][1], 0.f) * (1.f / DF);
            float d10 = fmaxf(x1 + y0 - 2.f * acc[mf][nf][2], 0.f) * (1.f / DF);
            float d11 = fmaxf(x1 + y1 - 2.f * acc[mf][nf][3], 0.f) * (1.f / DF);
            atomicAdd(&myh[min((int)(d00 * SC1), NB1 - 1)], wx0 * wy0);
            atomicAdd(&myh[min((int)(d01 * SC1), NB1 - 1)], wx0 * wy1);
            atomicAdd(&myh[min((int)(d10 * SC1), NB1 - 1)], wx1 * wy0);
            atomicAdd(&myh[min((int)(d11 * SC1), NB1 - 1)], wx1 * wy1);
        }
    }
    __syncthreads();
    float* hist = g_hcoarse + (ae ? 0 : NB1);
    for (int i = tid; i < NB1; i += 256) {
        float v = shh[i] + shh[i + NB1];
        if (v != 0.f) atomicAdd(&hist[i], v);
    }
}

// ---------------- scan coarse hist -> window (±16 bins) ----------------
__global__ void k_scan0() {
    int which = blockIdx.x;
    const float* h = g_hcoarse + which * NB1;
    __shared__ double part[256];
    int tid = threadIdx.x;
    double loc[8], s = 0.0;
    #pragma unroll
    for (int i = 0; i < 8; i++) { loc[i] = h[tid * 8 + i]; s += loc[i]; }
    part[tid] = s; __syncthreads();
    for (int off = 1; off < 256; off <<= 1) {
        double v = (tid >= off) ? part[tid - off] : 0.0;
        __syncthreads();
        part[tid] += v;
        __syncthreads();
    }
    double T = 0.5 * part[255];
    double c = tid ? part[tid - 1] : 0.0;
    int b = -1;
    #pragma unroll
    for (int i = 0; i < 8; i++) {
        double nc = c + loc[i];
        if (b < 0 && c < T && nc >= T) b = tid * 8 + i;
        c = nc;
    }
    if (b >= 0) {
        int blo = b > 16 ? b - 16 : 0;
        int bhi = b + 17 > NB1 ? NB1 : b + 17;
        g_scal[2 + 2 * which] = blo * (16.0 / NB1);
        g_scal[3 + 2 * which] = (bhi - blo) * (16.0 / NB1);
    }
}

// ---------------- refine via hi-only MMA recompute: below-mass + fine hist ----------------
#define ROF_X2    0
#define ROF_Y2    512
#define ROF_WX    1024
#define ROF_WY    1536
#define ROF_HIST  2048                      /* NBF*4 = 32768 */
#define ROF_TILES 34816
#define SMEM_RF   (ROF_TILES + 2 * TILE_BYTES)   /* 67584 */

__global__ void __launch_bounds__(256) k_refine_mma(
    const float* __restrict__ w, const float* __restrict__ ew)
{
    extern __shared__ __align__(128) char smem[];
    int tid = threadIdx.x;
    bool ae = (blockIdx.z == 0);
    int row0 = blockIdx.y * TB, col0 = blockIdx.x * TB;

    const __nv_bfloat16* Ah = ae ? g_hiA : g_hiB;
    const float* x2p = ae ? g_x2 : g_y2;
    const float* wxp = ae ? w : ew;
    int which = ae ? 0 : 1;

    float* shh = (float*)(smem + ROF_HIST);
    for (int i = tid; i < NBF; i += 256) shh[i] = 0.f;

    stage_one(smem + ROF_TILES,              Ah,    row0, 1, tid, 128);
    stage_one(smem + ROF_TILES + TILE_BYTES, g_hiB, col0, 1, tid, 128);
    if (tid < TB) {
        ((float*)(smem + ROF_X2))[tid] = x2p[row0 + tid];
        ((float*)(smem + ROF_WX))[tid] = wxp[row0 + tid];
        ((float*)(smem + ROF_Y2))[tid] = g_y2[col0 + tid];
        ((float*)(smem + ROF_WY))[tid] = ew[col0 + tid];
    }
    __syncthreads();

    uint32_t sT = (uint32_t)__cvta_generic_to_shared(smem) + ROF_TILES;
    float acc[4][4][4];
    mma_loop<4, false>(sT, 0, sT + TILE_BYTES, 0, tid, acc);

    const int lane = tid & 31, warp = tid >> 5;
    const int wr = warp >> 2, wc = warp & 3;
    const int g = lane >> 2, t = lane & 3;
    const float* x2s = (const float*)(smem + ROF_X2);
    const float* y2s = (const float*)(smem + ROF_Y2);
    const float* wxs = (const float*)(smem + ROF_WX);
    const float* wys = (const float*)(smem + ROF_WY);

    float lo    = (float)g_scal[2 + 2 * which];
    float scale = (float)((double)NBF / g_scal[3 + 2 * which]);
    float bacc = 0.f;

    #pragma unroll
    for (int mf = 0; mf < 4; mf++) {
        int r0 = wr * 64 + mf * 16 + g;
        float x0 = x2s[r0], x1 = x2s[r0 + 8];
        float wx0 = wxs[r0], wx1 = wxs[r0 + 8];
        #pragma unroll
        for (int nf = 0; nf < 4; nf++) {
            int c0 = wc * 32 + nf * 8 + 2 * t;
            float y0 = y2s[c0], y1 = y2s[c0 + 1];
            float wy0 = wys[c0], wy1 = wys[c0 + 1];
            float dd[4], wt[4];
            dd[0] = fmaxf(x0 + y0 - 2.f * acc[mf][nf][0], 0.f) * (1.f / DF); wt[0] = wx0 * wy0;
            dd[1] = fmaxf(x0 + y1 - 2.f * acc[mf][nf][1], 0.f) * (1.f / DF); wt[1] = wx0 * wy1;
            dd[2] = fmaxf(x1 + y0 - 2.f * acc[mf][nf][2], 0.f) * (1.f / DF); wt[2] = wx1 * wy0;
            dd[3] = fmaxf(x1 + y1 - 2.f * acc[mf][nf][3], 0.f) * (1.f / DF); wt[3] = wx1 * wy1;
            #pragma unroll
            for (int u = 0; u < 4; u++) {
                if (dd[u] < lo) bacc += wt[u];
                else {
                    int b = (int)((dd[u] - lo) * scale);
                    if (b < NBF) atomicAdd(&shh[b], wt[u]);
                }
            }
        }
    }
    __shared__ float red[256];
    red[tid] = bacc; __syncthreads();
    for (int off = 128; off; off >>= 1) {
        if (tid < off) red[tid] += red[tid + off];
        __syncthreads();
    }
    if (tid == 0) atomicAdd(&g_below[which], (double)red[0]);
    float* hist = g_hfine + which * NBF;
    for (int i = tid; i < NBF; i += 256) {
        float v = shh[i];
        if (v != 0.f) atomicAdd(&hist[i], v);
    }
}

// ---------------- scan fine hist -> g ----------------
__global__ void k_scanF() {
    int which = blockIdx.x;
    const float* h = g_hfine + which * NBF;
    __shared__ double part[1024];
    int tid = threadIdx.x;
    double loc[8], s = 0.0;
    #pragma unroll
    for (int i = 0; i < 8; i++) { loc[i] = h[tid * 8 + i]; s += loc[i]; }
    part[tid] = s; __syncthreads();
    for (int off = 1; off < 1024; off <<= 1) {
        double v = (tid >= off) ? part[tid - off] : 0.0;
        __syncthreads();
        part[tid] += v;
        __syncthreads();
    }
    double Wtot = (which == 0) ? g_scal[0] * g_scal[1] : g_scal[1] * g_scal[1];
    double T = 0.5 * Wtot - g_below[which];
    double lo = g_scal[2 + 2 * which], wdt = g_scal[3 + 2 * which];
    double c = tid ? part[tid - 1] : 0.0;
    int b = -1;
    #pragma unroll
    for (int i = 0; i < 8; i++) {
        double nc = c + loc[i];
        if (b < 0 && c < T && nc >= T) b = tid * 8 + i;
        c = nc;
    }
    if (tid == 0 && T <= 0.0) b = 0;
    if (tid == 1023 && T > 0.0 && part[1023] < T && b < 0) b = NBF - 1;
    if (b >= 0) {
        double tt = lo + (b + 0.5) * (wdt / NBF);
        g_scal[6 + which] = 1.0 / (tt + 1e-8);
    }
}

// ---------------- final fused: recompute tiles (3-product), K-weighted row sums ----------------
#define FOF_X2    0
#define FOF_Y2    512
#define FOF_W     1024
#define FOF_RS    1536
#define FOF_TILES 2048
#define SMEM_FIN  (FOF_TILES + 4 * TILE_BYTES)   /* 67584 */

__global__ void __launch_bounds__(256) k_final(
    const float* __restrict__ w, const float* __restrict__ ew)
{
    extern __shared__ __align__(128) char smem[];
    int tid = threadIdx.x;
    int row0 = blockIdx.y * TB, col0 = blockIdx.x * TB;
    bool ae = (blockIdx.z == 0);

    const __nv_bfloat16* Bh = ae ? g_hiB : g_hiA;
    const __nv_bfloat16* Bl = ae ? g_loB : g_loA;
    const float* y2p = ae ? g_y2 : g_x2;
    const float* wyp = ae ? ew : w;

    stage_one(smem + FOF_TILES,                  g_hiA, row0, 1, tid, 128);
    stage_one(smem + FOF_TILES + TILE_BYTES,     g_loA, row0, 1, tid, 128);
    stage_one(smem + FOF_TILES + 2 * TILE_BYTES, Bh,    col0, 1, tid, 128);
    stage_one(smem + FOF_TILES + 3 * TILE_BYTES, Bl,    col0, 1, tid, 128);
    if (tid < TB) {
        ((float*)(smem + FOF_X2))[tid] = g_x2[row0 + tid];
        ((float*)(smem + FOF_Y2))[tid] = y2p[col0 + tid];
        ((float*)(smem + FOF_W))[tid]  = wyp[col0 + tid];
        ((float*)(smem + FOF_RS))[tid] = 0.f;
    }
    __syncthreads();

    uint32_t sT = (uint32_t)__cvta_generic_to_shared(smem) + FOF_TILES;
    float acc[4][4][4];
    mma_loop<4, true>(sT, sT + TILE_BYTES, sT + 2 * TILE_BYTES, sT + 3 * TILE_BYTES, tid, acc);

    const int lane = tid & 31, warp = tid >> 5;
    const int wr = warp >> 2, wc = warp & 3;
    const int g = lane >> 2, t = lane & 3;
    const float* x2s = (const float*)(smem + FOF_X2);
    const float* y2s = (const float*)(smem + FOF_Y2);
    const float* ws  = (const float*)(smem + FOF_W);
    float* rowsum = (float*)(smem + FOF_RS);

    float G1 = (float)g_scal[6], G2 = (float)g_scal[7];

    #pragma unroll
    for (int mf = 0; mf < 4; mf++) {
        int r0 = wr * 64 + mf * 16 + g;
        float x0 = x2s[r0], x1 = x2s[r0 + 8];
        float p0 = 0.f, p1 = 0.f;
        #pragma unroll
        for (int nf = 0; nf < 4; nf++) {
            int c0 = wc * 32 + nf * 8 + 2 * t;
            float y0 = y2s[c0], y1 = y2s[c0 + 1];
            float w0 = ws[c0],  w1 = ws[c0 + 1];
            float d00 = fmaxf(x0 + y0 - 2.f * acc[mf][nf][0], 0.f) * (1.f / DF);
            float d01 = fmaxf(x0 + y1 - 2.f * acc[mf][nf][1], 0.f) * (1.f / DF);
            float d10 = fmaxf(x1 + y0 - 2.f * acc[mf][nf][2], 0.f) * (1.f / DF);
            float d11 = fmaxf(x1 + y1 - 2.f * acc[mf][nf][3], 0.f) * (1.f / DF);
            p0 += (__expf(-G1 * d00) + __expf(-G2 * d00)) * w0
                + (__expf(-G1 * d01) + __expf(-G2 * d01)) * w1;
            p1 += (__expf(-G1 * d10) + __expf(-G2 * d10)) * w0
                + (__expf(-G1 * d11) + __expf(-G2 * d11)) * w1;
        }
        atomicAdd(&rowsum[r0], p0);
        atomicAdd(&rowsum[r0 + 8], p1);
    }
    __syncthreads();
    if (tid < TB) {
        float* Sout = ae ? g_Sae : g_Saa;
        atomicAdd(&Sout[row0 + tid], rowsum[tid]);
    }
}

// ---------------- final combine ----------------
__global__ void k_combine(const float* __restrict__ w, float* __restrict__ out) {
    int i = blockIdx.x * blockDim.x + threadIdx.x;
    if (i < NPTS) {
        float Ws  = (float)g_scal[0];
        float EWs = (float)g_scal[1];
        out[i] = (w[i] / Ws) * (g_Sae[i] / EWs - g_Saa[i] / Ws);
    }
}

// ---------------- host launcher ----------------
extern "C" void kernel_launch(void* const* d_in, const int* in_sizes, int n_in,
                              void* d_out, int out_size)
{
    const float* state   = (const float*)d_in[0];
    const float* action  = (const float*)d_in[1];
    const float* estate  = (const float*)d_in[2];
    const float* eaction = (const float*)d_in[3];
    const float* w       = (const float*)d_in[4];
    const float* ew      = (const float*)d_in[5];
    float* out = (float*)d_out;

    cudaFuncSetAttribute(k_hist_sampled, cudaFuncAttributeMaxDynamicSharedMemorySize, SMEM_HS);
    cudaFuncSetAttribute(k_refine_mma,   cudaFuncAttributeMaxDynamicSharedMemorySize, SMEM_RF);
    cudaFuncSetAttribute(k_final,        cudaFuncAttributeMaxDynamicSharedMemorySize, SMEM_FIN);

    dim3 ghs(NTILE, 4, 2);
    dim3 gfull(NTILE, NTILE, 2);

    k_cvt<<<2048, 256>>>(state, action, estate, eaction);
    k_wsum<<<1, 1024>>>(w, ew);

    k_hist_sampled<<<ghs, 256, SMEM_HS>>>(w, ew);
    k_scan0<<<2, 256>>>();

    k_refine_mma<<<gfull, 256, SMEM_RF>>>(w, ew);
    k_scanF<<<2, 1024>>>();

    k_final<<<gfull, 256, SMEM_FIN>>>(w, ew);

    k_combine<<<16, 256>>>(w, out);
}